// round 1
// baseline (speedup 1.0000x reference)
#include <cuda_runtime.h>
#include <cuda_bf16.h>
#include <math.h>

// ---------------- problem constants ----------------
#define BATCH 4
#define C     256
#define NPIX  4096          // 64*64
#define GROUPS 32
#define CPG   (C/GROUPS)    // 8 channels per group
#define GELEMS (CPG*NPIX)   // 32768 elements per group
#define EPSV  1e-5f

// ---------------- scratch (device globals, no allocation) ----------------
__device__ float g_xn  [(size_t)BATCH*C*NPIX];            // 16 MB
__device__ float g_qkv [(size_t)BATCH*3*C*NPIX];          // 48 MB
__device__ float g_p   [(size_t)BATCH*NPIX*NPIX];         // 256 MB
__device__ float g_o   [(size_t)BATCH*C*NPIX];            // 16 MB
__device__ float g_mu  [BATCH*GROUPS];
__device__ float g_rstd[BATCH*GROUPS];

// ---------------- reductions ----------------
__device__ __forceinline__ float warpRedSum(float v) {
    #pragma unroll
    for (int o = 16; o > 0; o >>= 1) v += __shfl_xor_sync(0xffffffffu, v, o);
    return v;
}
__device__ __forceinline__ float warpRedMax(float v) {
    #pragma unroll
    for (int o = 16; o > 0; o >>= 1) v = fmaxf(v, __shfl_xor_sync(0xffffffffu, v, o));
    return v;
}

// ---------------- group-norm stats: one block per (b,g) ----------------
__global__ __launch_bounds__(256) void gn_stats_k(const float* __restrict__ x) {
    const int bg = blockIdx.x;                   // 0..127
    const float4* base = reinterpret_cast<const float4*>(x + (size_t)bg * GELEMS);
    float s = 0.f, ss = 0.f;
    for (int i = threadIdx.x; i < GELEMS / 4; i += 256) {
        float4 v = base[i];
        s  += v.x + v.y + v.z + v.w;
        ss += v.x*v.x + v.y*v.y + v.z*v.z + v.w*v.w;
    }
    __shared__ float shs[32], shss[32];
    float ws  = warpRedSum(s);
    float wss = warpRedSum(ss);
    const int lane = threadIdx.x & 31, wid = threadIdx.x >> 5;
    if (lane == 0) { shs[wid] = ws; shss[wid] = wss; }
    __syncthreads();
    if (wid == 0) {
        float a  = (lane < 8) ? shs[lane]  : 0.f;
        float b  = (lane < 8) ? shss[lane] : 0.f;
        a = warpRedSum(a); b = warpRedSum(b);
        if (lane == 0) {
            float mean = a * (1.f / (float)GELEMS);
            float var  = b * (1.f / (float)GELEMS) - mean * mean;
            g_mu[bg]   = mean;
            g_rstd[bg] = rsqrtf(var + EPSV);
        }
    }
}

// ---------------- group-norm apply (vectorized) ----------------
__global__ __launch_bounds__(256) void gn_apply_k(const float* __restrict__ x,
                                                  const float* __restrict__ gamma,
                                                  const float* __restrict__ beta) {
    const size_t i4 = (size_t)blockIdx.x * 256 + threadIdx.x;  // float4 index, 1048576 total
    const int c  = (int)((i4 >> 10) & (C - 1));   // 1024 float4 per channel row
    const int bg = (int)(i4 >> 13);               // 8192 float4 per group
    const float sc = gamma[c] * g_rstd[bg];
    const float sh = beta[c] - g_mu[bg] * sc;
    float4 v = reinterpret_cast<const float4*>(x)[i4];
    v.x = fmaf(v.x, sc, sh); v.y = fmaf(v.y, sc, sh);
    v.z = fmaf(v.z, sc, sh); v.w = fmaf(v.w, sc, sh);
    reinterpret_cast<float4*>(g_xn)[i4] = v;
}

// ---------------- generic tiled SGEMM ----------------
// C[m,n] = alpha * sum_k A(m,k) * B(k,n) (+ bias[m])
// A(m,k) = ATrans ? A[k*lda + m] : A[m*lda + k]
// B(k,n) = BTrans ? B[n*ldb + k] : B[k*ldb + n]
// All of M,N divisible by 128; K divisible by 16. batch via blockIdx.z with strides.
template<bool ATrans, bool BTrans, bool HasBias>
__global__ __launch_bounds__(256)
void sgemm_k(const float* __restrict__ A, const float* __restrict__ B,
             const float* __restrict__ bias, float* __restrict__ C_,
             int N_unused, int K, int lda, int ldb, int ldc,
             long long sA, long long sB, long long sC, float alpha)
{
    __shared__ float As[16][128];
    __shared__ float Bs[16][128];
    const int t  = threadIdx.x;
    const int bm = blockIdx.y * 128;
    const int bn = blockIdx.x * 128;
    A  += (long long)blockIdx.z * sA;
    B  += (long long)blockIdx.z * sB;
    C_ += (long long)blockIdx.z * sC;

    float acc[8][8];
    #pragma unroll
    for (int i = 0; i < 8; i++)
        #pragma unroll
        for (int j = 0; j < 8; j++) acc[i][j] = 0.f;

    const int ty = t >> 4, tx = t & 15;

    for (int k0 = 0; k0 < K; k0 += 16) {
        // ---- load A tile into As[k][m] ----
        if (ATrans) {
            #pragma unroll
            for (int r = 0; r < 2; r++) {
                int idx = t + r * 256;             // 0..511 float4 slots
                int kk  = idx >> 5;                // 16 rows
                int mm  = (idx & 31) << 2;         // 128 cols
                float4 v = *reinterpret_cast<const float4*>(
                    &A[(long long)(k0 + kk) * lda + bm + mm]);
                *reinterpret_cast<float4*>(&As[kk][mm]) = v;
            }
        } else {
            #pragma unroll
            for (int r = 0; r < 2; r++) {
                int idx = t + r * 256;
                int mm  = idx >> 2;                // 128 rows
                int kk  = (idx & 3) << 2;          // 16 cols
                float4 v = *reinterpret_cast<const float4*>(
                    &A[(long long)(bm + mm) * lda + k0 + kk]);
                As[kk + 0][mm] = v.x; As[kk + 1][mm] = v.y;
                As[kk + 2][mm] = v.z; As[kk + 3][mm] = v.w;
            }
        }
        // ---- load B tile into Bs[k][n] ----
        if (BTrans) {
            #pragma unroll
            for (int r = 0; r < 2; r++) {
                int idx = t + r * 256;
                int nn  = idx >> 2;
                int kk  = (idx & 3) << 2;
                float4 v = *reinterpret_cast<const float4*>(
                    &B[(long long)(bn + nn) * ldb + k0 + kk]);
                Bs[kk + 0][nn] = v.x; Bs[kk + 1][nn] = v.y;
                Bs[kk + 2][nn] = v.z; Bs[kk + 3][nn] = v.w;
            }
        } else {
            #pragma unroll
            for (int r = 0; r < 2; r++) {
                int idx = t + r * 256;
                int kk  = idx >> 5;
                int nn  = (idx & 31) << 2;
                float4 v = *reinterpret_cast<const float4*>(
                    &B[(long long)(k0 + kk) * ldb + bn + nn]);
                *reinterpret_cast<float4*>(&Bs[kk][nn]) = v;
            }
        }
        __syncthreads();
        #pragma unroll
        for (int kk = 0; kk < 16; kk++) {
            float a[8], b[8];
            *reinterpret_cast<float4*>(a)     = *reinterpret_cast<float4*>(&As[kk][ty * 8]);
            *reinterpret_cast<float4*>(a + 4) = *reinterpret_cast<float4*>(&As[kk][ty * 8 + 4]);
            *reinterpret_cast<float4*>(b)     = *reinterpret_cast<float4*>(&Bs[kk][tx * 8]);
            *reinterpret_cast<float4*>(b + 4) = *reinterpret_cast<float4*>(&Bs[kk][tx * 8 + 4]);
            #pragma unroll
            for (int i = 0; i < 8; i++)
                #pragma unroll
                for (int j = 0; j < 8; j++)
                    acc[i][j] = fmaf(a[i], b[j], acc[i][j]);
        }
        __syncthreads();
    }

    #pragma unroll
    for (int i = 0; i < 8; i++) {
        const int m = bm + ty * 8 + i;
        const float bv = HasBias ? bias[m] : 0.f;
        #pragma unroll
        for (int j = 0; j < 8; j += 4) {
            float4 v;
            v.x = fmaf(acc[i][j + 0], alpha, bv);
            v.y = fmaf(acc[i][j + 1], alpha, bv);
            v.z = fmaf(acc[i][j + 2], alpha, bv);
            v.w = fmaf(acc[i][j + 3], alpha, bv);
            *reinterpret_cast<float4*>(&C_[(long long)m * ldc + bn + tx * 8 + j]) = v;
        }
    }
}

// ---------------- row softmax over contiguous dim (n = 4096) ----------------
__global__ __launch_bounds__(256) void softmax_k() {
    float4* p = reinterpret_cast<float4*>(g_p) + (size_t)blockIdx.x * (NPIX / 4);
    const int t = threadIdx.x;
    float4 v[4];
    float mx = -INFINITY;
    #pragma unroll
    for (int r = 0; r < 4; r++) {
        v[r] = p[r * 256 + t];
        mx = fmaxf(mx, fmaxf(fmaxf(v[r].x, v[r].y), fmaxf(v[r].z, v[r].w)));
    }
    __shared__ float sh[32];
    float wm = warpRedMax(mx);
    const int lane = t & 31, wid = t >> 5;
    if (lane == 0) sh[wid] = wm;
    __syncthreads();
    if (wid == 0) {
        float a = (lane < 8) ? sh[lane] : -INFINITY;
        a = warpRedMax(a);
        if (lane == 0) sh[0] = a;
    }
    __syncthreads();
    mx = sh[0];
    __syncthreads();

    float sum = 0.f;
    #pragma unroll
    for (int r = 0; r < 4; r++) {
        v[r].x = __expf(v[r].x - mx); v[r].y = __expf(v[r].y - mx);
        v[r].z = __expf(v[r].z - mx); v[r].w = __expf(v[r].w - mx);
        sum += v[r].x + v[r].y + v[r].z + v[r].w;
    }
    float ws = warpRedSum(sum);
    if (lane == 0) sh[wid] = ws;
    __syncthreads();
    if (wid == 0) {
        float a = (lane < 8) ? sh[lane] : 0.f;
        a = warpRedSum(a);
        if (lane == 0) sh[0] = a;
    }
    __syncthreads();
    const float inv = 1.f / sh[0];
    #pragma unroll
    for (int r = 0; r < 4; r++) {
        v[r].x *= inv; v[r].y *= inv; v[r].z *= inv; v[r].w *= inv;
        p[r * 256 + t] = v[r];
    }
}

// ---------------- launch ----------------
extern "C" void kernel_launch(void* const* d_in, const int* in_sizes, int n_in,
                              void* d_out, int out_size) {
    (void)in_sizes; (void)n_in; (void)out_size;
    const float* x        = (const float*)d_in[0];
    const float* gn_gamma = (const float*)d_in[1];
    const float* gn_beta  = (const float*)d_in[2];
    const float* w_qkv    = (const float*)d_in[3];
    const float* b_qkv    = (const float*)d_in[4];
    const float* w_out    = (const float*)d_in[5];
    const float* b_out    = (const float*)d_in[6];
    float* out = (float*)d_out;

    float *xn, *qkv, *p, *o;
    cudaGetSymbolAddress((void**)&xn,  g_xn);
    cudaGetSymbolAddress((void**)&qkv, g_qkv);
    cudaGetSymbolAddress((void**)&p,   g_p);
    cudaGetSymbolAddress((void**)&o,   g_o);

    // 1) group-norm stats + apply
    gn_stats_k<<<BATCH * GROUPS, 256>>>(x);
    gn_apply_k<<<(BATCH * C * NPIX) / (4 * 256), 256>>>(x, gn_gamma, gn_beta);

    // 2) qkv = W_qkv[768,256] * XN[256,4096] + b_qkv  (per batch)
    {
        dim3 grid(NPIX / 128, (3 * C) / 128, BATCH);
        sgemm_k<false, false, true><<<grid, 256>>>(
            w_qkv, xn, b_qkv, qkv,
            NPIX, C, C, NPIX, NPIX,
            0LL, (long long)C * NPIX, (long long)3 * C * NPIX, 1.0f);
    }
    const float* q = qkv;                        // rows [0,256)
    const float* k = qkv + (size_t)C * NPIX;     // rows [256,512)
    const float* v = qkv + (size_t)2 * C * NPIX; // rows [512,768)

    // 3) P[j,i] = (1/16) * sum_c Q[c,j] * K[c,i]
    {
        dim3 grid(NPIX / 128, NPIX / 128, BATCH);
        sgemm_k<true, false, false><<<grid, 256>>>(
            q, k, nullptr, p,
            NPIX, C, NPIX, NPIX, NPIX,
            (long long)3 * C * NPIX, (long long)3 * C * NPIX,
            (long long)NPIX * NPIX, 0.0625f);
    }

    // 4) softmax over i (contiguous) for every (b, j) row
    softmax_k<<<BATCH * NPIX, 256>>>();

    // 5) O[c,j] = sum_i V[c,i] * P[j,i]
    {
        dim3 grid(NPIX / 128, C / 128, BATCH);
        sgemm_k<false, true, false><<<grid, 256>>>(
            v, p, nullptr, o,
            NPIX, NPIX, NPIX, NPIX, NPIX,
            (long long)3 * C * NPIX, (long long)NPIX * NPIX,
            (long long)C * NPIX, 1.0f);
    }

    // 6) out = W_out[256,256] * O[256,4096] + b_out
    {
        dim3 grid(NPIX / 128, C / 128, BATCH);
        sgemm_k<false, false, true><<<grid, 256>>>(
            w_out, o, b_out, out,
            NPIX, C, C, NPIX, NPIX,
            0LL, (long long)C * NPIX, (long long)C * NPIX, 1.0f);
    }
}

// round 4
// speedup vs baseline: 2.2385x; 2.2385x over previous
#include <cuda_runtime.h>
#include <cuda_bf16.h>
#include <math.h>
#include <stdint.h>

// ---------------- problem constants ----------------
#define BATCH 4
#define C     256
#define NPIX  4096          // 64*64
#define GROUPS 32
#define CPG   (C/GROUPS)    // 8 channels per group
#define GELEMS (CPG*NPIX)   // 32768 elements per group
#define EPSV  1e-5f

// ---------------- scratch (device globals, no allocation) ----------------
__device__ float g_xn  [(size_t)BATCH*C*NPIX];            // 16 MB
__device__ float g_qkv [(size_t)BATCH*3*C*NPIX];          // 48 MB
__device__ float g_qt  [(size_t)BATCH*NPIX*C];            // 16 MB  Q^T [n, c], tf32-rounded
__device__ float g_kt  [(size_t)BATCH*NPIX*C];            // 16 MB  K^T [n, c], tf32-rounded
__device__ float g_p   [(size_t)BATCH*NPIX*NPIX];         // 256 MB
__device__ float g_o   [(size_t)BATCH*C*NPIX];            // 16 MB
__device__ float g_mu  [BATCH*GROUPS];
__device__ float g_rstd[BATCH*GROUPS];

// ---------------- helpers ----------------
__device__ __forceinline__ float round_tf32(float v) {
    uint32_t b;
    asm("cvt.rna.tf32.f32 %0, %1;" : "=r"(b) : "f"(v));
    return __uint_as_float(b);
}

#define MMA_TF32(d, a, b) \
    asm volatile("mma.sync.aligned.m16n8k8.row.col.f32.tf32.tf32.f32 " \
        "{%0,%1,%2,%3}, {%4,%5,%6,%7}, {%8,%9}, {%0,%1,%2,%3};" \
        : "+f"((d)[0]), "+f"((d)[1]), "+f"((d)[2]), "+f"((d)[3]) \
        : "r"((a)[0]), "r"((a)[1]), "r"((a)[2]), "r"((a)[3]), \
          "r"((b)[0]), "r"((b)[1]))

__device__ __forceinline__ float warpRedSum(float v) {
    #pragma unroll
    for (int o = 16; o > 0; o >>= 1) v += __shfl_xor_sync(0xffffffffu, v, o);
    return v;
}
__device__ __forceinline__ float warpRedMax(float v) {
    #pragma unroll
    for (int o = 16; o > 0; o >>= 1) v = fmaxf(v, __shfl_xor_sync(0xffffffffu, v, o));
    return v;
}

// ---------------- group-norm stats ----------------
__global__ __launch_bounds__(256) void gn_stats_k(const float* __restrict__ x) {
    const int bg = blockIdx.x;
    const float4* base = reinterpret_cast<const float4*>(x + (size_t)bg * GELEMS);
    float s = 0.f, ss = 0.f;
    for (int i = threadIdx.x; i < GELEMS / 4; i += 256) {
        float4 v = base[i];
        s  += v.x + v.y + v.z + v.w;
        ss += v.x*v.x + v.y*v.y + v.z*v.z + v.w*v.w;
    }
    __shared__ float shs[32], shss[32];
    float ws = warpRedSum(s), wss = warpRedSum(ss);
    const int lane = threadIdx.x & 31, wid = threadIdx.x >> 5;
    if (lane == 0) { shs[wid] = ws; shss[wid] = wss; }
    __syncthreads();
    if (wid == 0) {
        float a = (lane < 8) ? shs[lane] : 0.f;
        float b = (lane < 8) ? shss[lane] : 0.f;
        a = warpRedSum(a); b = warpRedSum(b);
        if (lane == 0) {
            float mean = a * (1.f / (float)GELEMS);
            float var  = b * (1.f / (float)GELEMS) - mean * mean;
            g_mu[bg] = mean;
            g_rstd[bg] = rsqrtf(var + EPSV);
        }
    }
}

// ---------------- group-norm apply ----------------
__global__ __launch_bounds__(256) void gn_apply_k(const float* __restrict__ x,
                                                  const float* __restrict__ gamma,
                                                  const float* __restrict__ beta) {
    const size_t i4 = (size_t)blockIdx.x * 256 + threadIdx.x;
    const int c  = (int)((i4 >> 10) & (C - 1));
    const int bg = (int)(i4 >> 13);
    const float sc = gamma[c] * g_rstd[bg];
    const float sh = beta[c] - g_mu[bg] * sc;
    float4 v = reinterpret_cast<const float4*>(x)[i4];
    v.x = fmaf(v.x, sc, sh); v.y = fmaf(v.y, sc, sh);
    v.z = fmaf(v.z, sc, sh); v.w = fmaf(v.w, sc, sh);
    reinterpret_cast<float4*>(g_xn)[i4] = v;
}

// ---------------- fp32 SIMT SGEMM (qkv and out-proj; K=256) ----------------
template<bool HasBias>
__global__ __launch_bounds__(256)
void sgemm_k(const float* __restrict__ A, const float* __restrict__ B,
             const float* __restrict__ bias, float* __restrict__ C_,
             int K, int lda, int ldb, int ldc,
             long long sB, long long sC)
{
    __shared__ float As[16][128];
    __shared__ float Bs[16][128];
    const int t  = threadIdx.x;
    const int bm = blockIdx.y * 128;
    const int bn = blockIdx.x * 128;
    B  += (long long)blockIdx.z * sB;
    C_ += (long long)blockIdx.z * sC;

    float acc[8][8];
    #pragma unroll
    for (int i = 0; i < 8; i++)
        #pragma unroll
        for (int j = 0; j < 8; j++) acc[i][j] = 0.f;

    const int ty = t >> 4, tx = t & 15;

    for (int k0 = 0; k0 < K; k0 += 16) {
        #pragma unroll
        for (int r = 0; r < 2; r++) {
            int idx = t + r * 256;
            int mm  = idx >> 2;
            int kk  = (idx & 3) << 2;
            float4 v = *reinterpret_cast<const float4*>(&A[(long long)(bm + mm) * lda + k0 + kk]);
            As[kk + 0][mm] = v.x; As[kk + 1][mm] = v.y;
            As[kk + 2][mm] = v.z; As[kk + 3][mm] = v.w;
        }
        #pragma unroll
        for (int r = 0; r < 2; r++) {
            int idx = t + r * 256;
            int kk  = idx >> 5;
            int nn  = (idx & 31) << 2;
            float4 v = *reinterpret_cast<const float4*>(&B[(long long)(k0 + kk) * ldb + bn + nn]);
            *reinterpret_cast<float4*>(&Bs[kk][nn]) = v;
        }
        __syncthreads();
        #pragma unroll
        for (int kk = 0; kk < 16; kk++) {
            float a[8], b[8];
            *reinterpret_cast<float4*>(a)     = *reinterpret_cast<float4*>(&As[kk][ty * 8]);
            *reinterpret_cast<float4*>(a + 4) = *reinterpret_cast<float4*>(&As[kk][ty * 8 + 4]);
            *reinterpret_cast<float4*>(b)     = *reinterpret_cast<float4*>(&Bs[kk][tx * 8]);
            *reinterpret_cast<float4*>(b + 4) = *reinterpret_cast<float4*>(&Bs[kk][tx * 8 + 4]);
            #pragma unroll
            for (int i = 0; i < 8; i++)
                #pragma unroll
                for (int j = 0; j < 8; j++)
                    acc[i][j] = fmaf(a[i], b[j], acc[i][j]);
        }
        __syncthreads();
    }
    #pragma unroll
    for (int i = 0; i < 8; i++) {
        const int m = bm + ty * 8 + i;
        const float bv = HasBias ? bias[m] : 0.f;
        #pragma unroll
        for (int j = 0; j < 8; j += 4) {
            float4 v;
            v.x = acc[i][j + 0] + bv; v.y = acc[i][j + 1] + bv;
            v.z = acc[i][j + 2] + bv; v.w = acc[i][j + 3] + bv;
            *reinterpret_cast<float4*>(&C_[(long long)m * ldc + bn + tx * 8 + j]) = v;
        }
    }
}

// ---------------- transpose Q,K [C,N] -> [N,C], tf32-rounded ----------------
__global__ __launch_bounds__(256) void transpose_qk_k() {
    const int which = blockIdx.z & 1;       // 0=Q, 1=K
    const int b     = blockIdx.z >> 1;
    const float* src = g_qkv + (size_t)b * 3 * C * NPIX + (size_t)which * C * NPIX;
    float* dst = (which ? g_kt : g_qt) + (size_t)b * NPIX * C;
    __shared__ float tile[32][33];
    const int n0 = blockIdx.x * 32, c0 = blockIdx.y * 32;
    const int tx = threadIdx.x & 31, ty = threadIdx.x >> 5;   // 32 x 8
    #pragma unroll
    for (int i = ty; i < 32; i += 8)
        tile[i][tx] = src[(size_t)(c0 + i) * NPIX + n0 + tx];
    __syncthreads();
    #pragma unroll
    for (int i = ty; i < 32; i += 8)
        dst[(size_t)(n0 + i) * C + c0 + tx] = round_tf32(tile[tx][i]);
}

// ---------------- round V in place to tf32 ----------------
__global__ __launch_bounds__(256) void round_v_k() {
    float* v = g_qkv + (size_t)blockIdx.z * 3 * C * NPIX + (size_t)2 * C * NPIX;
    const size_t i4 = (size_t)blockIdx.x * 256 + threadIdx.x;
    float4 x = reinterpret_cast<float4*>(v)[i4];
    x.x = round_tf32(x.x); x.y = round_tf32(x.y);
    x.z = round_tf32(x.z); x.w = round_tf32(x.w);
    reinterpret_cast<float4*>(v)[i4] = x;
}

// ---------------- tensor-core tf32 GEMM via mma.sync (m16n8k8) ----------------
// D[m,n] = alpha * sum_k A[m,k] * B[n,k]   (A row-major k-contig, B row-major k-contig)
// Block tile 128x128, KTILE=32, 8 warps (4m x 2n), warp tile 32x64.
// Smem stride 36 floats: conflict-free scalar fragment LDS.
#define KTILE 32
#define SSTR  36
#define STG_F (128 * SSTR)                  // floats per stage per operand

__global__ __launch_bounds__(256, 1)
void mma_gemm_k(const float* __restrict__ A, const float* __restrict__ B,
                float* __restrict__ Cg, int lda, int ldb, int ldc, int K,
                long long sA, long long sB, long long sC, float alpha)
{
    extern __shared__ float sm[];           // As[2][128][36] | Bs[2][128][36]
    float* Asm = sm;
    float* Bsm = sm + 2 * STG_F;

    const int t = threadIdx.x, wid = t >> 5, lane = t & 31;
    const int g = lane >> 2, tq = lane & 3;
    const int wm = (wid >> 1) * 32;         // 4 warps along m
    const int wn = (wid & 1) * 64;          // 2 warps along n
    const int bm = blockIdx.y * 128;
    const int bn = blockIdx.x * 128;
    A  += (long long)blockIdx.z * sA + (long long)bm * lda;
    B  += (long long)blockIdx.z * sB + (long long)bn * ldb;
    Cg += (long long)blockIdx.z * sC;

    const int lr = t >> 3;                  // load row (0..31), +32 per chunk
    const int lc = (t & 7) << 2;            // load col (0,4,...,28)

    float acc[2][8][4];
    #pragma unroll
    for (int i = 0; i < 2; i++)
        #pragma unroll
        for (int j = 0; j < 8; j++)
            #pragma unroll
            for (int r = 0; r < 4; r++) acc[i][j][r] = 0.f;

    float4 ra[4], rb[4];

    // prologue: load k-tile 0
    #pragma unroll
    for (int i = 0; i < 4; i++) {
        ra[i] = *reinterpret_cast<const float4*>(&A[(long long)(lr + 32 * i) * lda + lc]);
        rb[i] = *reinterpret_cast<const float4*>(&B[(long long)(lr + 32 * i) * ldb + lc]);
    }
    #pragma unroll
    for (int i = 0; i < 4; i++) {
        float* pa = &Asm[(lr + 32 * i) * SSTR + lc];
        float* pb = &Bsm[(lr + 32 * i) * SSTR + lc];
        *reinterpret_cast<float2*>(pa)     = make_float2(ra[i].x, ra[i].y);
        *reinterpret_cast<float2*>(pa + 2) = make_float2(ra[i].z, ra[i].w);
        *reinterpret_cast<float2*>(pb)     = make_float2(rb[i].x, rb[i].y);
        *reinterpret_cast<float2*>(pb + 2) = make_float2(rb[i].z, rb[i].w);
    }
    __syncthreads();

    const int T = K / KTILE;
    int buf = 0;
    for (int kt = 0; kt < T; kt++) {
        if (kt + 1 < T) {
            const int k0 = (kt + 1) * KTILE;
            #pragma unroll
            for (int i = 0; i < 4; i++) {
                ra[i] = *reinterpret_cast<const float4*>(&A[(long long)(lr + 32 * i) * lda + k0 + lc]);
                rb[i] = *reinterpret_cast<const float4*>(&B[(long long)(lr + 32 * i) * ldb + k0 + lc]);
            }
        }

        // compute on buf
        {
            const float* Ab = Asm + buf * STG_F;
            const float* Bb = Bsm + buf * STG_F;
            #pragma unroll
            for (int c8 = 0; c8 < KTILE; c8 += 8) {
                uint32_t af[2][4], bf[8][2];
                #pragma unroll
                for (int mf = 0; mf < 2; mf++) {
                    const int r0 = wm + mf * 16 + g;
                    af[mf][0] = __float_as_uint(Ab[r0 * SSTR + c8 + tq]);
                    af[mf][1] = __float_as_uint(Ab[(r0 + 8) * SSTR + c8 + tq]);
                    af[mf][2] = __float_as_uint(Ab[r0 * SSTR + c8 + tq + 4]);
                    af[mf][3] = __float_as_uint(Ab[(r0 + 8) * SSTR + c8 + tq + 4]);
                }
                #pragma unroll
                for (int nf = 0; nf < 8; nf++) {
                    const int n0 = wn + nf * 8 + g;
                    bf[nf][0] = __float_as_uint(Bb[n0 * SSTR + c8 + tq]);
                    bf[nf][1] = __float_as_uint(Bb[n0 * SSTR + c8 + tq + 4]);
                }
                #pragma unroll
                for (int mf = 0; mf < 2; mf++)
                    #pragma unroll
                    for (int nf = 0; nf < 8; nf++)
                        MMA_TF32(acc[mf][nf], af[mf], bf[nf]);
            }
        }

        if (kt + 1 < T) {
            float* Ab = Asm + (buf ^ 1) * STG_F;
            float* Bb = Bsm + (buf ^ 1) * STG_F;
            #pragma unroll
            for (int i = 0; i < 4; i++) {
                float* pa = &Ab[(lr + 32 * i) * SSTR + lc];
                float* pb = &Bb[(lr + 32 * i) * SSTR + lc];
                *reinterpret_cast<float2*>(pa)     = make_float2(ra[i].x, ra[i].y);
                *reinterpret_cast<float2*>(pa + 2) = make_float2(ra[i].z, ra[i].w);
                *reinterpret_cast<float2*>(pb)     = make_float2(rb[i].x, rb[i].y);
                *reinterpret_cast<float2*>(pb + 2) = make_float2(rb[i].z, rb[i].w);
            }
        }
        __syncthreads();
        buf ^= 1;
    }

    // epilogue: direct v2 global stores (each STG.64 = 8 fully-used 32B sectors)
    #pragma unroll
    for (int mf = 0; mf < 2; mf++)
        #pragma unroll
        for (int h = 0; h < 2; h++) {
            const long long row = bm + wm + mf * 16 + g + 8 * h;
            #pragma unroll
            for (int nf = 0; nf < 8; nf++) {
                float2 v;
                v.x = acc[mf][nf][2 * h]     * alpha;
                v.y = acc[mf][nf][2 * h + 1] * alpha;
                *reinterpret_cast<float2*>(&Cg[row * ldc + bn + wn + nf * 8 + 2 * tq]) = v;
            }
        }
}

// ---------------- row softmax, tf32-rounded output ----------------
__global__ __launch_bounds__(256) void softmax_k() {
    float4* p = reinterpret_cast<float4*>(g_p) + (size_t)blockIdx.x * (NPIX / 4);
    const int t = threadIdx.x;
    float4 v[4];
    float mx = -INFINITY;
    #pragma unroll
    for (int r = 0; r < 4; r++) {
        v[r] = p[r * 256 + t];
        mx = fmaxf(mx, fmaxf(fmaxf(v[r].x, v[r].y), fmaxf(v[r].z, v[r].w)));
    }
    __shared__ float sh[32];
    float wm = warpRedMax(mx);
    const int lane = t & 31, wid = t >> 5;
    if (lane == 0) sh[wid] = wm;
    __syncthreads();
    if (wid == 0) {
        float a = (lane < 8) ? sh[lane] : -INFINITY;
        a = warpRedMax(a);
        if (lane == 0) sh[0] = a;
    }
    __syncthreads();
    mx = sh[0];
    __syncthreads();

    float sum = 0.f;
    #pragma unroll
    for (int r = 0; r < 4; r++) {
        v[r].x = __expf(v[r].x - mx); v[r].y = __expf(v[r].y - mx);
        v[r].z = __expf(v[r].z - mx); v[r].w = __expf(v[r].w - mx);
        sum += v[r].x + v[r].y + v[r].z + v[r].w;
    }
    float ws = warpRedSum(sum);
    if (lane == 0) sh[wid] = ws;
    __syncthreads();
    if (wid == 0) {
        float a = (lane < 8) ? sh[lane] : 0.f;
        a = warpRedSum(a);
        if (lane == 0) sh[0] = a;
    }
    __syncthreads();
    const float inv = 1.f / sh[0];
    #pragma unroll
    for (int r = 0; r < 4; r++) {
        v[r].x = round_tf32(v[r].x * inv); v[r].y = round_tf32(v[r].y * inv);
        v[r].z = round_tf32(v[r].z * inv); v[r].w = round_tf32(v[r].w * inv);
        p[r * 256 + t] = v[r];
    }
}

// ---------------- launch ----------------
extern "C" void kernel_launch(void* const* d_in, const int* in_sizes, int n_in,
                              void* d_out, int out_size) {
    (void)in_sizes; (void)n_in; (void)out_size;
    const float* x        = (const float*)d_in[0];
    const float* gn_gamma = (const float*)d_in[1];
    const float* gn_beta  = (const float*)d_in[2];
    const float* w_qkv    = (const float*)d_in[3];
    const float* b_qkv    = (const float*)d_in[4];
    const float* w_out    = (const float*)d_in[5];
    const float* b_out    = (const float*)d_in[6];
    float* out = (float*)d_out;

    float *xn, *qkv, *p, *o, *qt, *kt;
    cudaGetSymbolAddress((void**)&xn,  g_xn);
    cudaGetSymbolAddress((void**)&qkv, g_qkv);
    cudaGetSymbolAddress((void**)&p,   g_p);
    cudaGetSymbolAddress((void**)&o,   g_o);
    cudaGetSymbolAddress((void**)&qt,  g_qt);
    cudaGetSymbolAddress((void**)&kt,  g_kt);

    const int SMEM_MMA = 4 * STG_F * (int)sizeof(float);   // 73728 B
    cudaFuncSetAttribute(mma_gemm_k, cudaFuncAttributeMaxDynamicSharedMemorySize, SMEM_MMA);

    // 1) group norm
    gn_stats_k<<<BATCH * GROUPS, 256>>>(x);
    gn_apply_k<<<(BATCH * C * NPIX) / (4 * 256), 256>>>(x, gn_gamma, gn_beta);

    // 2) qkv = W_qkv[768,256] * XN[256,4096] + b  (fp32 SIMT)
    {
        dim3 grid(NPIX / 128, (3 * C) / 128, BATCH);
        sgemm_k<true><<<grid, 256>>>(w_qkv, xn, b_qkv, qkv,
                                     C, C, NPIX, NPIX,
                                     (long long)C * NPIX, (long long)3 * C * NPIX);
    }
    const float* v = qkv + (size_t)2 * C * NPIX;

    // 3) transpose+round Q,K -> Qt[n,c], Kt[n,c]; round V in place
    transpose_qk_k<<<dim3(NPIX / 32, C / 32, BATCH * 2), 256>>>();
    round_v_k<<<dim3((C * NPIX) / (4 * 256), 1, BATCH), 256>>>();

    // 4) scores: P[j,i] = (1/16) * Qt[j,:] . Kt[i,:]   (tensor tf32)
    {
        dim3 grid(NPIX / 128, NPIX / 128, BATCH);
        mma_gemm_k<<<grid, 256, SMEM_MMA>>>(
            qt, kt, p, C, C, NPIX, C,
            (long long)NPIX * C, (long long)NPIX * C, (long long)NPIX * NPIX, 0.0625f);
    }

    // 5) softmax over i (contiguous), output rounded to tf32
    softmax_k<<<BATCH * NPIX, 256>>>();

    // 6) O[c,j] = V[c,:] . P[j,:]   (tensor tf32)
    {
        dim3 grid(NPIX / 128, C / 128, BATCH);
        mma_gemm_k<<<grid, 256, SMEM_MMA>>>(
            v, p, o, NPIX, NPIX, NPIX, NPIX,
            (long long)3 * C * NPIX, (long long)NPIX * NPIX, (long long)C * NPIX, 1.0f);
    }

    // 7) out = W_out[256,256] * O[256,4096] + b_out  (fp32 SIMT)
    {
        dim3 grid(NPIX / 128, C / 128, BATCH);
        sgemm_k<true><<<grid, 256>>>(w_out, o, b_out, out,
                                     C, C, NPIX, NPIX,
                                     (long long)C * NPIX, (long long)C * NPIX);
    }
}

// round 5
// speedup vs baseline: 2.6480x; 1.1829x over previous
#include <cuda_runtime.h>
#include <cuda_bf16.h>
#include <math.h>
#include <stdint.h>

// ---------------- problem constants ----------------
#define BATCH 4
#define C     256
#define NPIX  4096          // 64*64
#define GROUPS 32
#define CPG   (C/GROUPS)    // 8 channels per group
#define GELEMS (CPG*NPIX)   // 32768 elements per group
#define EPSV  1e-5f

// ---------------- scratch (device globals, no allocation) ----------------
__device__ float g_xnt [(size_t)BATCH*NPIX*C];            // 16 MB  xn^T [n, c], tf32
__device__ float g_qkv [(size_t)BATCH*3*C*NPIX];          // 48 MB  [o, n]
__device__ float g_qt  [(size_t)BATCH*NPIX*C];            // 16 MB  Q^T [n, c], tf32
__device__ float g_kt  [(size_t)BATCH*NPIX*C];            // 16 MB  K^T [n, c], tf32
__device__ float g_p   [(size_t)BATCH*NPIX*NPIX];         // 256 MB
__device__ float g_ot  [(size_t)BATCH*NPIX*C];            // 16 MB  O^T [j, c], tf32
__device__ float g_wq  [3*C*C];                           // W_qkv tf32-rounded
__device__ float g_wo  [C*C];                             // W_out tf32-rounded
__device__ float g_mu  [BATCH*GROUPS];
__device__ float g_rstd[BATCH*GROUPS];

// ---------------- helpers ----------------
__device__ __forceinline__ float round_tf32(float v) {
    uint32_t b;
    asm("cvt.rna.tf32.f32 %0, %1;" : "=r"(b) : "f"(v));
    return __uint_as_float(b);
}

#define MMA_TF32(d, a, b) \
    asm volatile("mma.sync.aligned.m16n8k8.row.col.f32.tf32.tf32.f32 " \
        "{%0,%1,%2,%3}, {%4,%5,%6,%7}, {%8,%9}, {%0,%1,%2,%3};" \
        : "+f"((d)[0]), "+f"((d)[1]), "+f"((d)[2]), "+f"((d)[3]) \
        : "r"((a)[0]), "r"((a)[1]), "r"((a)[2]), "r"((a)[3]), \
          "r"((b)[0]), "r"((b)[1]))

__device__ __forceinline__ float warpRedSum(float v) {
    #pragma unroll
    for (int o = 16; o > 0; o >>= 1) v += __shfl_xor_sync(0xffffffffu, v, o);
    return v;
}
__device__ __forceinline__ float warpRedMax(float v) {
    #pragma unroll
    for (int o = 16; o > 0; o >>= 1) v = fmaxf(v, __shfl_xor_sync(0xffffffffu, v, o));
    return v;
}

// ---------------- group-norm stats ----------------
__global__ __launch_bounds__(256) void gn_stats_k(const float* __restrict__ x) {
    const int bg = blockIdx.x;
    const float4* base = reinterpret_cast<const float4*>(x + (size_t)bg * GELEMS);
    float s = 0.f, ss = 0.f;
    for (int i = threadIdx.x; i < GELEMS / 4; i += 256) {
        float4 v = base[i];
        s  += v.x + v.y + v.z + v.w;
        ss += v.x*v.x + v.y*v.y + v.z*v.z + v.w*v.w;
    }
    __shared__ float shs[32], shss[32];
    float ws = warpRedSum(s), wss = warpRedSum(ss);
    const int lane = threadIdx.x & 31, wid = threadIdx.x >> 5;
    if (lane == 0) { shs[wid] = ws; shss[wid] = wss; }
    __syncthreads();
    if (wid == 0) {
        float a = (lane < 8) ? shs[lane] : 0.f;
        float b = (lane < 8) ? shss[lane] : 0.f;
        a = warpRedSum(a); b = warpRedSum(b);
        if (lane == 0) {
            float mean = a * (1.f / (float)GELEMS);
            float var  = b * (1.f / (float)GELEMS) - mean * mean;
            g_mu[bg] = mean;
            g_rstd[bg] = rsqrtf(var + EPSV);
        }
    }
}

// ---------------- group-norm apply + transpose: x[c,n] -> xnT[n,c] (tf32) ----------------
__global__ __launch_bounds__(256) void gn_apply_t_k(const float* __restrict__ x,
                                                    const float* __restrict__ gamma,
                                                    const float* __restrict__ beta) {
    const int b  = blockIdx.z;
    const int n0 = blockIdx.x * 32, c0 = blockIdx.y * 32;
    const float* src = x + (size_t)b * C * NPIX;
    float* dst = g_xnt + (size_t)b * NPIX * C;
    __shared__ float tile[32][33];
    const int tx = threadIdx.x & 31, ty = threadIdx.x >> 5;   // 32 x 8
    #pragma unroll
    for (int i = ty; i < 32; i += 8) {
        const int c = c0 + i;
        const int bg = b * GROUPS + (c >> 3);                 // 8 channels per group
        const float sc = gamma[c] * g_rstd[bg];
        const float sh = beta[c] - g_mu[bg] * sc;
        tile[i][tx] = round_tf32(fmaf(src[(size_t)c * NPIX + n0 + tx], sc, sh));
    }
    __syncthreads();
    #pragma unroll
    for (int i = ty; i < 32; i += 8)
        dst[(size_t)(n0 + i) * C + c0 + tx] = tile[tx][i];
}

// ---------------- round both weight matrices to tf32 ----------------
__global__ __launch_bounds__(256) void round_w_k(const float* __restrict__ wq,
                                                 const float* __restrict__ wo) {
    const int i4 = blockIdx.x * 256 + threadIdx.x;            // 65536 float4 total
    const int WQ4 = 3 * C * C / 4;                            // 49152
    float4 v;
    if (i4 < WQ4) v = reinterpret_cast<const float4*>(wq)[i4];
    else          v = reinterpret_cast<const float4*>(wo)[i4 - WQ4];
    v.x = round_tf32(v.x); v.y = round_tf32(v.y);
    v.z = round_tf32(v.z); v.w = round_tf32(v.w);
    if (i4 < WQ4) reinterpret_cast<float4*>(g_wq)[i4] = v;
    else          reinterpret_cast<float4*>(g_wo)[i4 - WQ4] = v;
}

// ---------------- transpose Q,K [C,N] -> [N,C], tf32-rounded ----------------
__global__ __launch_bounds__(256) void transpose_qk_k() {
    const int which = blockIdx.z & 1;       // 0=Q, 1=K
    const int b     = blockIdx.z >> 1;
    const float* src = g_qkv + (size_t)b * 3 * C * NPIX + (size_t)which * C * NPIX;
    float* dst = (which ? g_kt : g_qt) + (size_t)b * NPIX * C;
    __shared__ float tile[32][33];
    const int n0 = blockIdx.x * 32, c0 = blockIdx.y * 32;
    const int tx = threadIdx.x & 31, ty = threadIdx.x >> 5;   // 32 x 8
    #pragma unroll
    for (int i = ty; i < 32; i += 8)
        tile[i][tx] = src[(size_t)(c0 + i) * NPIX + n0 + tx];
    __syncthreads();
    #pragma unroll
    for (int i = ty; i < 32; i += 8)
        dst[(size_t)(n0 + i) * C + c0 + tx] = round_tf32(tile[tx][i]);
}

// ---------------- round V in place to tf32 ----------------
__global__ __launch_bounds__(256) void round_v_k() {
    float* v = g_qkv + (size_t)blockIdx.z * 3 * C * NPIX + (size_t)2 * C * NPIX;
    const size_t i4 = (size_t)blockIdx.x * 256 + threadIdx.x;
    float4 x = reinterpret_cast<float4*>(v)[i4];
    x.x = round_tf32(x.x); x.y = round_tf32(x.y);
    x.z = round_tf32(x.z); x.w = round_tf32(x.w);
    reinterpret_cast<float4*>(v)[i4] = x;
}

// ---------------- tensor-core tf32 GEMM via mma.sync (m16n8k8) ----------------
// D[m,n] = alpha * sum_k A[m,k] * B[n,k] (+ bias[m]) [optional tf32-round of D]
// Block tile 128x128, KTILE=32, 8 warps (4m x 2n), warp tile 32x64.
#define KTILE 32
#define SSTR  36
#define STG_F (128 * SSTR)                  // floats per stage per operand

template<bool HasBias, bool RoundOut>
__global__ __launch_bounds__(256, 1)
void mma_gemm_k(const float* __restrict__ A, const float* __restrict__ B,
                const float* __restrict__ bias, float* __restrict__ Cg,
                int lda, int ldb, int ldc, int K,
                long long sA, long long sB, long long sC, float alpha)
{
    extern __shared__ float sm[];           // As[2][128][36] | Bs[2][128][36]
    float* Asm = sm;
    float* Bsm = sm + 2 * STG_F;

    const int t = threadIdx.x, wid = t >> 5, lane = t & 31;
    const int g = lane >> 2, tq = lane & 3;
    const int wm = (wid >> 1) * 32;         // 4 warps along m
    const int wn = (wid & 1) * 64;          // 2 warps along n
    const int bm = blockIdx.y * 128;
    const int bn = blockIdx.x * 128;
    A  += (long long)blockIdx.z * sA + (long long)bm * lda;
    B  += (long long)blockIdx.z * sB + (long long)bn * ldb;
    Cg += (long long)blockIdx.z * sC;

    const int lr = t >> 3;                  // load row (0..31), +32 per chunk
    const int lc = (t & 7) << 2;            // load col (0,4,...,28)

    float acc[2][8][4];
    #pragma unroll
    for (int i = 0; i < 2; i++)
        #pragma unroll
        for (int j = 0; j < 8; j++)
            #pragma unroll
            for (int r = 0; r < 4; r++) acc[i][j][r] = 0.f;

    float4 ra[4], rb[4];

    // prologue: load k-tile 0
    #pragma unroll
    for (int i = 0; i < 4; i++) {
        ra[i] = *reinterpret_cast<const float4*>(&A[(long long)(lr + 32 * i) * lda + lc]);
        rb[i] = *reinterpret_cast<const float4*>(&B[(long long)(lr + 32 * i) * ldb + lc]);
    }
    #pragma unroll
    for (int i = 0; i < 4; i++) {
        float* pa = &Asm[(lr + 32 * i) * SSTR + lc];
        float* pb = &Bsm[(lr + 32 * i) * SSTR + lc];
        *reinterpret_cast<float2*>(pa)     = make_float2(ra[i].x, ra[i].y);
        *reinterpret_cast<float2*>(pa + 2) = make_float2(ra[i].z, ra[i].w);
        *reinterpret_cast<float2*>(pb)     = make_float2(rb[i].x, rb[i].y);
        *reinterpret_cast<float2*>(pb + 2) = make_float2(rb[i].z, rb[i].w);
    }
    __syncthreads();

    const int T = K / KTILE;
    int buf = 0;
    for (int kt = 0; kt < T; kt++) {
        if (kt + 1 < T) {
            const int k0 = (kt + 1) * KTILE;
            #pragma unroll
            for (int i = 0; i < 4; i++) {
                ra[i] = *reinterpret_cast<const float4*>(&A[(long long)(lr + 32 * i) * lda + k0 + lc]);
                rb[i] = *reinterpret_cast<const float4*>(&B[(long long)(lr + 32 * i) * ldb + k0 + lc]);
            }
        }

        // compute on buf
        {
            const float* Ab = Asm + buf * STG_F;
            const float* Bb = Bsm + buf * STG_F;
            #pragma unroll
            for (int c8 = 0; c8 < KTILE; c8 += 8) {
                uint32_t af[2][4], bf[8][2];
                #pragma unroll
                for (int mf = 0; mf < 2; mf++) {
                    const int r0 = wm + mf * 16 + g;
                    af[mf][0] = __float_as_uint(Ab[r0 * SSTR + c8 + tq]);
                    af[mf][1] = __float_as_uint(Ab[(r0 + 8) * SSTR + c8 + tq]);
                    af[mf][2] = __float_as_uint(Ab[r0 * SSTR + c8 + tq + 4]);
                    af[mf][3] = __float_as_uint(Ab[(r0 + 8) * SSTR + c8 + tq + 4]);
                }
                #pragma unroll
                for (int nf = 0; nf < 8; nf++) {
                    const int n0 = wn + nf * 8 + g;
                    bf[nf][0] = __float_as_uint(Bb[n0 * SSTR + c8 + tq]);
                    bf[nf][1] = __float_as_uint(Bb[n0 * SSTR + c8 + tq + 4]);
                }
                #pragma unroll
                for (int mf = 0; mf < 2; mf++)
                    #pragma unroll
                    for (int nf = 0; nf < 8; nf++)
                        MMA_TF32(acc[mf][nf], af[mf], bf[nf]);
            }
        }

        if (kt + 1 < T) {
            float* Ab = Asm + (buf ^ 1) * STG_F;
            float* Bb = Bsm + (buf ^ 1) * STG_F;
            #pragma unroll
            for (int i = 0; i < 4; i++) {
                float* pa = &Ab[(lr + 32 * i) * SSTR + lc];
                float* pb = &Bb[(lr + 32 * i) * SSTR + lc];
                *reinterpret_cast<float2*>(pa)     = make_float2(ra[i].x, ra[i].y);
                *reinterpret_cast<float2*>(pa + 2) = make_float2(ra[i].z, ra[i].w);
                *reinterpret_cast<float2*>(pb)     = make_float2(rb[i].x, rb[i].y);
                *reinterpret_cast<float2*>(pb + 2) = make_float2(rb[i].z, rb[i].w);
            }
        }
        __syncthreads();
        buf ^= 1;
    }

    // epilogue: direct v2 global stores
    #pragma unroll
    for (int mf = 0; mf < 2; mf++)
        #pragma unroll
        for (int h = 0; h < 2; h++) {
            const long long row = bm + wm + mf * 16 + g + 8 * h;
            const float bv = HasBias ? __ldg(&bias[row]) : 0.f;
            #pragma unroll
            for (int nf = 0; nf < 8; nf++) {
                float2 v;
                v.x = fmaf(acc[mf][nf][2 * h],     alpha, bv);
                v.y = fmaf(acc[mf][nf][2 * h + 1], alpha, bv);
                if (RoundOut) { v.x = round_tf32(v.x); v.y = round_tf32(v.y); }
                *reinterpret_cast<float2*>(&Cg[row * ldc + bn + wn + nf * 8 + 2 * tq]) = v;
            }
        }
}

// ---------------- row softmax, tf32-rounded output ----------------
__global__ __launch_bounds__(256) void softmax_k() {
    float4* p = reinterpret_cast<float4*>(g_p) + (size_t)blockIdx.x * (NPIX / 4);
    const int t = threadIdx.x;
    float4 v[4];
    float mx = -INFINITY;
    #pragma unroll
    for (int r = 0; r < 4; r++) {
        v[r] = p[r * 256 + t];
        mx = fmaxf(mx, fmaxf(fmaxf(v[r].x, v[r].y), fmaxf(v[r].z, v[r].w)));
    }
    __shared__ float sh[32];
    float wm = warpRedMax(mx);
    const int lane = t & 31, wid = t >> 5;
    if (lane == 0) sh[wid] = wm;
    __syncthreads();
    if (wid == 0) {
        float a = (lane < 8) ? sh[lane] : -INFINITY;
        a = warpRedMax(a);
        if (lane == 0) sh[0] = a;
    }
    __syncthreads();
    mx = sh[0];
    __syncthreads();

    float sum = 0.f;
    #pragma unroll
    for (int r = 0; r < 4; r++) {
        v[r].x = __expf(v[r].x - mx); v[r].y = __expf(v[r].y - mx);
        v[r].z = __expf(v[r].z - mx); v[r].w = __expf(v[r].w - mx);
        sum += v[r].x + v[r].y + v[r].z + v[r].w;
    }
    float ws = warpRedSum(sum);
    if (lane == 0) sh[wid] = ws;
    __syncthreads();
    if (wid == 0) {
        float a = (lane < 8) ? sh[lane] : 0.f;
        a = warpRedSum(a);
        if (lane == 0) sh[0] = a;
    }
    __syncthreads();
    const float inv = 1.f / sh[0];
    #pragma unroll
    for (int r = 0; r < 4; r++) {
        v[r].x = round_tf32(v[r].x * inv); v[r].y = round_tf32(v[r].y * inv);
        v[r].z = round_tf32(v[r].z * inv); v[r].w = round_tf32(v[r].w * inv);
        p[r * 256 + t] = v[r];
    }
}

// ---------------- launch ----------------
extern "C" void kernel_launch(void* const* d_in, const int* in_sizes, int n_in,
                              void* d_out, int out_size) {
    (void)in_sizes; (void)n_in; (void)out_size;
    const float* x        = (const float*)d_in[0];
    const float* gn_gamma = (const float*)d_in[1];
    const float* gn_beta  = (const float*)d_in[2];
    const float* w_qkv    = (const float*)d_in[3];
    const float* b_qkv    = (const float*)d_in[4];
    const float* w_out    = (const float*)d_in[5];
    const float* b_out    = (const float*)d_in[6];
    float* out = (float*)d_out;

    float *xnt, *qkv, *p, *ot, *qt, *kt, *wq, *wo;
    cudaGetSymbolAddress((void**)&xnt, g_xnt);
    cudaGetSymbolAddress((void**)&qkv, g_qkv);
    cudaGetSymbolAddress((void**)&p,   g_p);
    cudaGetSymbolAddress((void**)&ot,  g_ot);
    cudaGetSymbolAddress((void**)&qt,  g_qt);
    cudaGetSymbolAddress((void**)&kt,  g_kt);
    cudaGetSymbolAddress((void**)&wq,  g_wq);
    cudaGetSymbolAddress((void**)&wo,  g_wo);

    const int SMEM_MMA = 4 * STG_F * (int)sizeof(float);   // 73728 B
    cudaFuncSetAttribute(mma_gemm_k<true,  false>, cudaFuncAttributeMaxDynamicSharedMemorySize, SMEM_MMA);
    cudaFuncSetAttribute(mma_gemm_k<false, false>, cudaFuncAttributeMaxDynamicSharedMemorySize, SMEM_MMA);
    cudaFuncSetAttribute(mma_gemm_k<false, true >, cudaFuncAttributeMaxDynamicSharedMemorySize, SMEM_MMA);

    // 1) group norm stats; weight rounding (independent)
    gn_stats_k<<<BATCH * GROUPS, 256>>>(x);
    round_w_k<<<256, 256>>>(w_qkv, w_out);

    // 2) GN apply + transpose -> xnT [n, c] (tf32)
    gn_apply_t_k<<<dim3(NPIX / 32, C / 32, BATCH), 256>>>(x, gn_gamma, gn_beta);

    // 3) qkv[o,n] = Wqkv[o,c] . xnT[n,c]^T + b_qkv   (tensor tf32)
    {
        dim3 grid(NPIX / 128, (3 * C) / 128, BATCH);
        mma_gemm_k<true, false><<<grid, 256, SMEM_MMA>>>(
            wq, xnt, b_qkv, qkv, C, C, NPIX, C,
            0LL, (long long)NPIX * C, (long long)3 * C * NPIX, 1.0f);
    }
    const float* v = qkv + (size_t)2 * C * NPIX;

    // 4) transpose+round Q,K -> Qt[n,c], Kt[n,c]; round V in place
    transpose_qk_k<<<dim3(NPIX / 32, C / 32, BATCH * 2), 256>>>();
    round_v_k<<<dim3((C * NPIX) / (4 * 256), 1, BATCH), 256>>>();

    // 5) scores: P[j,i] = (1/16) * Qt[j,:] . Kt[i,:]   (tensor tf32)
    {
        dim3 grid(NPIX / 128, NPIX / 128, BATCH);
        mma_gemm_k<false, false><<<grid, 256, SMEM_MMA>>>(
            qt, kt, nullptr, p, C, C, NPIX, C,
            (long long)NPIX * C, (long long)NPIX * C, (long long)NPIX * NPIX, 0.0625f);
    }

    // 6) softmax over i (contiguous), output rounded to tf32
    softmax_k<<<BATCH * NPIX, 256>>>();

    // 7) O^T[j,c] = P[j,:] . V[c,:]^T   (tensor tf32, rounded output)
    {
        dim3 grid(C / 128, NPIX / 128, BATCH);
        mma_gemm_k<false, true><<<grid, 256, SMEM_MMA>>>(
            p, v, nullptr, ot, NPIX, NPIX, C, NPIX,
            (long long)NPIX * NPIX, (long long)3 * C * NPIX, (long long)NPIX * C, 1.0f);
    }

    // 8) out[o,j] = Wout[o,c] . OT[j,c]^T + b_out   (tensor tf32)
    {
        dim3 grid(NPIX / 128, C / 128, BATCH);
        mma_gemm_k<true, false><<<grid, 256, SMEM_MMA>>>(
            wo, ot, b_out, out, C, C, NPIX, C,
            0LL, (long long)NPIX * C, (long long)C * NPIX, 1.0f);
    }
}

// round 7
// speedup vs baseline: 4.2034x; 1.5874x over previous
#include <cuda_runtime.h>
#include <cuda_fp16.h>
#include <math.h>
#include <stdint.h>

// ---------------- problem constants ----------------
#define BATCH 4
#define C     256
#define NPIX  4096          // 64*64
#define GROUPS 32
#define GELEMS ((C/GROUPS)*NPIX)   // 32768 elements per group
#define EPSV  1e-5f

// ---------------- scratch (device globals, no allocation) ----------------
__device__ __half g_xnt[(size_t)BATCH*NPIX*C];            // 8 MB   xn^T [n, c] half
__device__ float  g_qkv[(size_t)BATCH*3*C*NPIX];          // 48 MB  [o, n] fp32
__device__ __half g_qth[(size_t)BATCH*NPIX*C];            // 8 MB   Q^T [n, c] half
__device__ __half g_kth[(size_t)BATCH*NPIX*C];            // 8 MB   K^T [n, c] half
__device__ __half g_vh [(size_t)BATCH*C*NPIX];            // 8 MB   V [c, n] half
__device__ float  g_p  [(size_t)BATCH*NPIX*NPIX];         // 256 MB scores fp32
__device__ __half g_ph [(size_t)BATCH*NPIX*NPIX];         // 128 MB probs half
__device__ __half g_oth[(size_t)BATCH*NPIX*C];            // 8 MB   O^T [j, c] half
__device__ __half g_wqh[3*C*C];                           // W_qkv half
__device__ __half g_woh[C*C];                             // W_out half
__device__ float  g_mu  [BATCH*GROUPS];
__device__ float  g_rstd[BATCH*GROUPS];

// ---------------- helpers ----------------
#define MMA_F16(d, a, b) \
    asm volatile("mma.sync.aligned.m16n8k16.row.col.f32.f16.f16.f32 " \
        "{%0,%1,%2,%3}, {%4,%5,%6,%7}, {%8,%9}, {%0,%1,%2,%3};" \
        : "+f"((d)[0]), "+f"((d)[1]), "+f"((d)[2]), "+f"((d)[3]) \
        : "r"((a)[0]), "r"((a)[1]), "r"((a)[2]), "r"((a)[3]), \
          "r"((b)[0]), "r"((b)[1]))

__device__ __forceinline__ float warpRedSum(float v) {
    #pragma unroll
    for (int o = 16; o > 0; o >>= 1) v += __shfl_xor_sync(0xffffffffu, v, o);
    return v;
}
__device__ __forceinline__ float warpRedMax(float v) {
    #pragma unroll
    for (int o = 16; o > 0; o >>= 1) v = fmaxf(v, __shfl_xor_sync(0xffffffffu, v, o));
    return v;
}

// ---------------- group-norm stats ----------------
__global__ __launch_bounds__(256) void gn_stats_k(const float* __restrict__ x) {
    const int bg = blockIdx.x;
    const float4* base = reinterpret_cast<const float4*>(x + (size_t)bg * GELEMS);
    float s = 0.f, ss = 0.f;
    for (int i = threadIdx.x; i < GELEMS / 4; i += 256) {
        float4 v = base[i];
        s  += v.x + v.y + v.z + v.w;
        ss += v.x*v.x + v.y*v.y + v.z*v.z + v.w*v.w;
    }
    __shared__ float shs[32], shss[32];
    float ws = warpRedSum(s), wss = warpRedSum(ss);
    const int lane = threadIdx.x & 31, wid = threadIdx.x >> 5;
    if (lane == 0) { shs[wid] = ws; shss[wid] = wss; }
    __syncthreads();
    if (wid == 0) {
        float a = (lane < 8) ? shs[lane] : 0.f;
        float b = (lane < 8) ? shss[lane] : 0.f;
        a = warpRedSum(a); b = warpRedSum(b);
        if (lane == 0) {
            float mean = a * (1.f / (float)GELEMS);
            float var  = b * (1.f / (float)GELEMS) - mean * mean;
            g_mu[bg] = mean;
            g_rstd[bg] = rsqrtf(var + EPSV);
        }
    }
}

// ---------------- convert weights to half ----------------
__global__ __launch_bounds__(256) void conv_w_k(const float* __restrict__ wq,
                                                const float* __restrict__ wo) {
    const int i4 = blockIdx.x * 256 + threadIdx.x;            // 65536 float4 total
    const int WQ4 = 3 * C * C / 4;                            // 49152
    float4 v;
    if (i4 < WQ4) v = reinterpret_cast<const float4*>(wq)[i4];
    else          v = reinterpret_cast<const float4*>(wo)[i4 - WQ4];
    __half2 h0 = __floats2half2_rn(v.x, v.y);
    __half2 h1 = __floats2half2_rn(v.z, v.w);
    __half* dst = (i4 < WQ4) ? (g_wqh + (size_t)i4 * 4) : (g_woh + (size_t)(i4 - WQ4) * 4);
    *reinterpret_cast<__half2*>(dst)     = h0;
    *reinterpret_cast<__half2*>(dst + 2) = h1;
}

// ---------------- group-norm apply + transpose: x[c,n] -> xnT[n,c] (half) ----------------
__global__ __launch_bounds__(256) void gn_apply_t_k(const float* __restrict__ x,
                                                    const float* __restrict__ gamma,
                                                    const float* __restrict__ beta) {
    const int b  = blockIdx.z;
    const int n0 = blockIdx.x * 32, c0 = blockIdx.y * 32;
    const float* src = x + (size_t)b * C * NPIX;
    __half* dst = g_xnt + (size_t)b * NPIX * C;
    __shared__ float tile[32][33];
    const int tx = threadIdx.x & 31, ty = threadIdx.x >> 5;   // 32 x 8
    #pragma unroll
    for (int i = ty; i < 32; i += 8) {
        const int c = c0 + i;
        const int bg = b * GROUPS + (c >> 3);                 // 8 channels per group
        const float sc = gamma[c] * g_rstd[bg];
        const float sh = beta[c] - g_mu[bg] * sc;
        tile[i][tx] = fmaf(src[(size_t)c * NPIX + n0 + tx], sc, sh);
    }
    __syncthreads();
    #pragma unroll
    for (int i = ty; i < 32; i += 8)
        dst[(size_t)(n0 + i) * C + c0 + tx] = __float2half_rn(tile[tx][i]);
}

// ---------------- transpose Q,K [C,N] fp32 -> [N,C] half ----------------
__global__ __launch_bounds__(256) void transpose_qk_k() {
    const int which = blockIdx.z & 1;       // 0=Q, 1=K
    const int b     = blockIdx.z >> 1;
    const float* src = g_qkv + (size_t)b * 3 * C * NPIX + (size_t)which * C * NPIX;
    __half* dst = (which ? g_kth : g_qth) + (size_t)b * NPIX * C;
    __shared__ float tile[32][33];
    const int n0 = blockIdx.x * 32, c0 = blockIdx.y * 32;
    const int tx = threadIdx.x & 31, ty = threadIdx.x >> 5;   // 32 x 8
    #pragma unroll
    for (int i = ty; i < 32; i += 8)
        tile[i][tx] = src[(size_t)(c0 + i) * NPIX + n0 + tx];
    __syncthreads();
    #pragma unroll
    for (int i = ty; i < 32; i += 8)
        dst[(size_t)(n0 + i) * C + c0 + tx] = __float2half_rn(tile[tx][i]);
}

// ---------------- convert V [c,n] fp32 -> half ----------------
__global__ __launch_bounds__(256) void conv_v_k() {
    const float* v = g_qkv + (size_t)blockIdx.z * 3 * C * NPIX + (size_t)2 * C * NPIX;
    __half* vh = g_vh + (size_t)blockIdx.z * C * NPIX;
    const size_t i4 = (size_t)blockIdx.x * 256 + threadIdx.x;
    float4 x = reinterpret_cast<const float4*>(v)[i4];
    *reinterpret_cast<__half2*>(vh + i4 * 4)     = __floats2half2_rn(x.x, x.y);
    *reinterpret_cast<__half2*>(vh + i4 * 4 + 2) = __floats2half2_rn(x.z, x.w);
}

// ---------------- fp16 tensor GEMM via mma.sync (m16n8k16) ----------------
// D[m,n] = alpha * sum_k A[m,k] * B[n,k] (+ bias[m]); output fp32 or half.
// Block tile 128x128, KTILE=32 halves, 8 warps (4m x 2n), warp tile 32x64.
#define HKT  32
#define HSTR 40
#define HSTG (128 * HSTR)                   // halves per stage per operand

template<bool HasBias, bool OutHalf>
__global__ __launch_bounds__(256)
void hgemm_k(const __half* __restrict__ A, const __half* __restrict__ B,
             const float* __restrict__ bias, void* __restrict__ Cg,
             int lda, int ldb, int ldc, int K,
             long long sA, long long sB, long long sC, float alpha)
{
    __shared__ __half sm[4 * HSTG];         // As0 Bs0 As1 Bs1 = 40960 B

    const int t = threadIdx.x, wid = t >> 5, lane = t & 31;
    const int g = lane >> 2, tq = lane & 3;
    const int wm = (wid >> 1) * 32;         // 4 warps along m
    const int wn = (wid & 1) * 64;          // 2 warps along n
    const int bm = blockIdx.y * 128;
    const int bn = blockIdx.x * 128;
    A += (long long)blockIdx.z * sA + (long long)bm * lda;
    B += (long long)blockIdx.z * sB + (long long)bn * ldb;

    const int lr = t >> 2;                  // load row (0..63), +64 per half
    const int lch = (t & 3) << 3;           // load col halves (0,8,16,24)

    float acc[2][8][4];
    #pragma unroll
    for (int i = 0; i < 2; i++)
        #pragma unroll
        for (int j = 0; j < 8; j++)
            #pragma unroll
            for (int r = 0; r < 4; r++) acc[i][j][r] = 0.f;

    uint4 ra[2], rb[2];

    // prologue: load k-tile 0
    #pragma unroll
    for (int i = 0; i < 2; i++) {
        ra[i] = *reinterpret_cast<const uint4*>(&A[(long long)(lr + 64 * i) * lda + lch]);
        rb[i] = *reinterpret_cast<const uint4*>(&B[(long long)(lr + 64 * i) * ldb + lch]);
    }
    #pragma unroll
    for (int i = 0; i < 2; i++) {
        *reinterpret_cast<uint4*>(&sm[(lr + 64 * i) * HSTR + lch])            = ra[i];
        *reinterpret_cast<uint4*>(&sm[HSTG + (lr + 64 * i) * HSTR + lch])     = rb[i];
    }
    __syncthreads();

    const int T = K / HKT;
    int buf = 0;
    for (int kt = 0; kt < T; kt++) {
        if (kt + 1 < T) {
            const int k0 = (kt + 1) * HKT;
            #pragma unroll
            for (int i = 0; i < 2; i++) {
                ra[i] = *reinterpret_cast<const uint4*>(&A[(long long)(lr + 64 * i) * lda + k0 + lch]);
                rb[i] = *reinterpret_cast<const uint4*>(&B[(long long)(lr + 64 * i) * ldb + k0 + lch]);
            }
        }

        // compute on buf
        {
            const __half* Ab = sm + buf * 2 * HSTG;
            const __half* Bb = Ab + HSTG;
            #pragma unroll
            for (int ks = 0; ks < HKT; ks += 16) {
                uint32_t af[2][4], bf[8][2];
                #pragma unroll
                for (int mf = 0; mf < 2; mf++) {
                    const int r0 = wm + mf * 16 + g;
                    af[mf][0] = *reinterpret_cast<const uint32_t*>(&Ab[r0 * HSTR + ks + 2 * tq]);
                    af[mf][1] = *reinterpret_cast<const uint32_t*>(&Ab[(r0 + 8) * HSTR + ks + 2 * tq]);
                    af[mf][2] = *reinterpret_cast<const uint32_t*>(&Ab[r0 * HSTR + ks + 2 * tq + 8]);
                    af[mf][3] = *reinterpret_cast<const uint32_t*>(&Ab[(r0 + 8) * HSTR + ks + 2 * tq + 8]);
                }
                #pragma unroll
                for (int nf = 0; nf < 8; nf++) {
                    const int n0 = wn + nf * 8 + g;
                    bf[nf][0] = *reinterpret_cast<const uint32_t*>(&Bb[n0 * HSTR + ks + 2 * tq]);
                    bf[nf][1] = *reinterpret_cast<const uint32_t*>(&Bb[n0 * HSTR + ks + 2 * tq + 8]);
                }
                #pragma unroll
                for (int mf = 0; mf < 2; mf++)
                    #pragma unroll
                    for (int nf = 0; nf < 8; nf++)
                        MMA_F16(acc[mf][nf], af[mf], bf[nf]);
            }
        }

        if (kt + 1 < T) {
            __half* Ab = sm + (buf ^ 1) * 2 * HSTG;
            __half* Bb = Ab + HSTG;
            #pragma unroll
            for (int i = 0; i < 2; i++) {
                *reinterpret_cast<uint4*>(&Ab[(lr + 64 * i) * HSTR + lch]) = ra[i];
                *reinterpret_cast<uint4*>(&Bb[(lr + 64 * i) * HSTR + lch]) = rb[i];
            }
        }
        __syncthreads();
        buf ^= 1;
    }

    // epilogue
    #pragma unroll
    for (int mf = 0; mf < 2; mf++)
        #pragma unroll
        for (int h = 0; h < 2; h++) {
            const long long row = bm + wm + mf * 16 + g + 8 * h;
            const float bv = HasBias ? __ldg(&bias[row]) : 0.f;
            #pragma unroll
            for (int nf = 0; nf < 8; nf++) {
                const long long col = bn + wn + nf * 8 + 2 * tq;
                float vx = fmaf(acc[mf][nf][2 * h],     alpha, bv);
                float vy = fmaf(acc[mf][nf][2 * h + 1], alpha, bv);
                if (OutHalf) {
                    __half* Ch = (__half*)Cg + (long long)blockIdx.z * sC;
                    *reinterpret_cast<__half2*>(&Ch[row * ldc + col]) = __floats2half2_rn(vx, vy);
                } else {
                    float* Cf = (float*)Cg + (long long)blockIdx.z * sC;
                    *reinterpret_cast<float2*>(&Cf[row * ldc + col]) = make_float2(vx, vy);
                }
            }
        }
}

// ---------------- row softmax: fp32 in, half out ----------------
__global__ __launch_bounds__(256) void softmax_k() {
    const float4* p = reinterpret_cast<const float4*>(g_p) + (size_t)blockIdx.x * (NPIX / 4);
    __half* ph = g_ph + (size_t)blockIdx.x * NPIX;
    const int t = threadIdx.x;
    float4 v[4];
    float mx = -INFINITY;
    #pragma unroll
    for (int r = 0; r < 4; r++) {
        v[r] = p[r * 256 + t];
        mx = fmaxf(mx, fmaxf(fmaxf(v[r].x, v[r].y), fmaxf(v[r].z, v[r].w)));
    }
    __shared__ float sh[32];
    float wm = warpRedMax(mx);
    const int lane = t & 31, wid = t >> 5;
    if (lane == 0) sh[wid] = wm;
    __syncthreads();
    if (wid == 0) {
        float a = (lane < 8) ? sh[lane] : -INFINITY;
        a = warpRedMax(a);
        if (lane == 0) sh[0] = a;
    }
    __syncthreads();
    mx = sh[0];
    __syncthreads();

    float sum = 0.f;
    #pragma unroll
    for (int r = 0; r < 4; r++) {
        v[r].x = __expf(v[r].x - mx); v[r].y = __expf(v[r].y - mx);
        v[r].z = __expf(v[r].z - mx); v[r].w = __expf(v[r].w - mx);
        sum += v[r].x + v[r].y + v[r].z + v[r].w;
    }
    float ws = warpRedSum(sum);
    if (lane == 0) sh[wid] = ws;
    __syncthreads();
    if (wid == 0) {
        float a = (lane < 8) ? sh[lane] : 0.f;
        a = warpRedSum(a);
        if (lane == 0) sh[0] = a;
    }
    __syncthreads();
    const float inv = 1.f / sh[0];
    #pragma unroll
    for (int r = 0; r < 4; r++) {
        const size_t e = (size_t)(r * 256 + t) * 4;
        *reinterpret_cast<__half2*>(&ph[e])     = __floats2half2_rn(v[r].x * inv, v[r].y * inv);
        *reinterpret_cast<__half2*>(&ph[e + 2]) = __floats2half2_rn(v[r].z * inv, v[r].w * inv);
    }
}

// ---------------- launch ----------------
extern "C" void kernel_launch(void* const* d_in, const int* in_sizes, int n_in,
                              void* d_out, int out_size) {
    (void)in_sizes; (void)n_in; (void)out_size;
    const float* x        = (const float*)d_in[0];
    const float* gn_gamma = (const float*)d_in[1];
    const float* gn_beta  = (const float*)d_in[2];
    const float* w_qkv    = (const float*)d_in[3];
    const float* b_qkv    = (const float*)d_in[4];
    const float* w_out    = (const float*)d_in[5];
    const float* b_out    = (const float*)d_in[6];
    float* out = (float*)d_out;

    __half *xnt, *qth, *kth, *vh, *ph, *oth, *wqh, *woh;
    float *qkv, *p;
    cudaGetSymbolAddress((void**)&xnt, g_xnt);
    cudaGetSymbolAddress((void**)&qkv, g_qkv);
    cudaGetSymbolAddress((void**)&qth, g_qth);
    cudaGetSymbolAddress((void**)&kth, g_kth);
    cudaGetSymbolAddress((void**)&vh,  g_vh);
    cudaGetSymbolAddress((void**)&p,   g_p);
    cudaGetSymbolAddress((void**)&ph,  g_ph);
    cudaGetSymbolAddress((void**)&oth, g_oth);
    cudaGetSymbolAddress((void**)&wqh, g_wqh);
    cudaGetSymbolAddress((void**)&woh, g_woh);

    // 1) group-norm stats; weight conversion (independent)
    gn_stats_k<<<BATCH * GROUPS, 256>>>(x);
    conv_w_k<<<256, 256>>>(w_qkv, w_out);

    // 2) GN apply + transpose -> xnT [n, c] half
    gn_apply_t_k<<<dim3(NPIX / 32, C / 32, BATCH), 256>>>(x, gn_gamma, gn_beta);

    // 3) qkv[o,n] fp32 = Wqkv[o,c] . xnT[n,c]^T + b_qkv
    hgemm_k<true, false><<<dim3(NPIX / 128, (3 * C) / 128, BATCH), 256>>>(
        wqh, xnt, b_qkv, qkv, C, C, NPIX, C,
        0LL, (long long)NPIX * C, (long long)3 * C * NPIX, 1.0f);

    // 4) transpose Q,K -> half [n,c]; convert V -> half
    transpose_qk_k<<<dim3(NPIX / 32, C / 32, BATCH * 2), 256>>>();
    conv_v_k<<<dim3((C * NPIX) / (4 * 256), 1, BATCH), 256>>>();

    // 5) scores: P[j,i] fp32 = (1/16) * Qt[j,:] . Kt[i,:]
    hgemm_k<false, false><<<dim3(NPIX / 128, NPIX / 128, BATCH), 256>>>(
        qth, kth, nullptr, p, C, C, NPIX, C,
        (long long)NPIX * C, (long long)NPIX * C, (long long)NPIX * NPIX, 0.0625f);

    // 6) softmax over i (contiguous): fp32 -> half probs
    softmax_k<<<BATCH * NPIX, 256>>>();

    // 7) O^T[j,c] half = P[j,:] . V[c,:]^T    (K = 4096)
    hgemm_k<false, true><<<dim3(C / 128, NPIX / 128, BATCH), 256>>>(
        ph, vh, nullptr, oth, NPIX, NPIX, C, NPIX,
        (long long)NPIX * NPIX, (long long)C * NPIX, (long long)NPIX * C, 1.0f);

    // 8) out[o,j] fp32 = Wout[o,c] . OT[j,c]^T + b_out
    hgemm_k<true, false><<<dim3(NPIX / 128, C / 128, BATCH), 256>>>(
        woh, oth, b_out, out, C, C, NPIX, C,
        0LL, (long long)NPIX * C, (long long)C * NPIX, 1.0f);
}

// round 8
// speedup vs baseline: 4.6382x; 1.1034x over previous
#include <cuda_runtime.h>
#include <cuda_fp16.h>
#include <math.h>
#include <stdint.h>

// ---------------- problem constants ----------------
#define BATCH 4
#define C     256
#define NPIX  4096          // 64*64
#define GROUPS 32
#define GELEMS ((C/GROUPS)*NPIX)   // 32768 elements per group
#define EPSV  1e-5f
#define EXP_SHIFT 4.0f      // softmax fixed shift: e^(s-4); safe for s_max in (-inf, ~15]

// ---------------- scratch (device globals, no allocation) ----------------
__device__ __half g_xnt [(size_t)BATCH*NPIX*C];           // 8 MB   xn^T [n, c] half
__device__ __half g_qkvh[(size_t)BATCH*3*C*NPIX];         // 24 MB  qkv [o, n] half
__device__ __half g_qth [(size_t)BATCH*NPIX*C];           // 8 MB   Q^T [n, c] half
__device__ __half g_kth [(size_t)BATCH*NPIX*C];           // 8 MB   K^T [n, c] half
__device__ __half g_ph  [(size_t)BATCH*NPIX*NPIX];        // 128 MB unnormalized probs half
__device__ __half g_oth [(size_t)BATCH*NPIX*C];           // 8 MB   O^T [j, c] half
__device__ __half g_wqh [3*C*C];                          // W_qkv half
__device__ __half g_woh [C*C];                            // W_out half
__device__ float  g_partial[(size_t)64*BATCH*NPIX];       // 4 MB   per-(i-slot) row sums
__device__ float  g_rowsum [(size_t)BATCH*NPIX];          // 64 KB  softmax denominators
__device__ float  g_mu  [BATCH*GROUPS];
__device__ float  g_rstd[BATCH*GROUPS];

// ---------------- helpers ----------------
#define MMA_F16(d, a, b) \
    asm volatile("mma.sync.aligned.m16n8k16.row.col.f32.f16.f16.f32 " \
        "{%0,%1,%2,%3}, {%4,%5,%6,%7}, {%8,%9}, {%0,%1,%2,%3};" \
        : "+f"((d)[0]), "+f"((d)[1]), "+f"((d)[2]), "+f"((d)[3]) \
        : "r"((a)[0]), "r"((a)[1]), "r"((a)[2]), "r"((a)[3]), \
          "r"((b)[0]), "r"((b)[1]))

__device__ __forceinline__ float warpRedSum(float v) {
    #pragma unroll
    for (int o = 16; o > 0; o >>= 1) v += __shfl_xor_sync(0xffffffffu, v, o);
    return v;
}

// ---------------- group-norm stats ----------------
__global__ __launch_bounds__(256) void gn_stats_k(const float* __restrict__ x) {
    const int bg = blockIdx.x;
    const float4* base = reinterpret_cast<const float4*>(x + (size_t)bg * GELEMS);
    float s = 0.f, ss = 0.f;
    for (int i = threadIdx.x; i < GELEMS / 4; i += 256) {
        float4 v = base[i];
        s  += v.x + v.y + v.z + v.w;
        ss += v.x*v.x + v.y*v.y + v.z*v.z + v.w*v.w;
    }
    __shared__ float shs[32], shss[32];
    float ws = warpRedSum(s), wss = warpRedSum(ss);
    const int lane = threadIdx.x & 31, wid = threadIdx.x >> 5;
    if (lane == 0) { shs[wid] = ws; shss[wid] = wss; }
    __syncthreads();
    if (wid == 0) {
        float a = (lane < 8) ? shs[lane] : 0.f;
        float b = (lane < 8) ? shss[lane] : 0.f;
        a = warpRedSum(a); b = warpRedSum(b);
        if (lane == 0) {
            float mean = a * (1.f / (float)GELEMS);
            float var  = b * (1.f / (float)GELEMS) - mean * mean;
            g_mu[bg] = mean;
            g_rstd[bg] = rsqrtf(var + EPSV);
        }
    }
}

// ---------------- convert weights to half ----------------
__global__ __launch_bounds__(256) void conv_w_k(const float* __restrict__ wq,
                                                const float* __restrict__ wo) {
    const int i4 = blockIdx.x * 256 + threadIdx.x;            // 65536 float4 total
    const int WQ4 = 3 * C * C / 4;                            // 49152
    float4 v;
    if (i4 < WQ4) v = reinterpret_cast<const float4*>(wq)[i4];
    else          v = reinterpret_cast<const float4*>(wo)[i4 - WQ4];
    __half2 h0 = __floats2half2_rn(v.x, v.y);
    __half2 h1 = __floats2half2_rn(v.z, v.w);
    __half* dst = (i4 < WQ4) ? (g_wqh + (size_t)i4 * 4) : (g_woh + (size_t)(i4 - WQ4) * 4);
    *reinterpret_cast<__half2*>(dst)     = h0;
    *reinterpret_cast<__half2*>(dst + 2) = h1;
}

// ---------------- group-norm apply + transpose: x[c,n] -> xnT[n,c] (half) ----------------
__global__ __launch_bounds__(256) void gn_apply_t_k(const float* __restrict__ x,
                                                    const float* __restrict__ gamma,
                                                    const float* __restrict__ beta) {
    const int b  = blockIdx.z;
    const int n0 = blockIdx.x * 32, c0 = blockIdx.y * 32;
    const float* src = x + (size_t)b * C * NPIX;
    __half* dst = g_xnt + (size_t)b * NPIX * C;
    __shared__ float tile[32][33];
    const int tx = threadIdx.x & 31, ty = threadIdx.x >> 5;   // 32 x 8
    #pragma unroll
    for (int i = ty; i < 32; i += 8) {
        const int c = c0 + i;
        const int bg = b * GROUPS + (c >> 3);                 // 8 channels per group
        const float sc = gamma[c] * g_rstd[bg];
        const float sh = beta[c] - g_mu[bg] * sc;
        tile[i][tx] = fmaf(src[(size_t)c * NPIX + n0 + tx], sc, sh);
    }
    __syncthreads();
    #pragma unroll
    for (int i = ty; i < 32; i += 8)
        dst[(size_t)(n0 + i) * C + c0 + tx] = __float2half_rn(tile[tx][i]);
}

// ---------------- transpose Q,K [C,N] half -> [N,C] half ----------------
__global__ __launch_bounds__(256) void transpose_qk_k() {
    const int which = blockIdx.z & 1;       // 0=Q, 1=K
    const int b     = blockIdx.z >> 1;
    const __half* src = g_qkvh + (size_t)b * 3 * C * NPIX + (size_t)which * C * NPIX;
    __half* dst = (which ? g_kth : g_qth) + (size_t)b * NPIX * C;
    __shared__ __half tile[32][34];
    const int n0 = blockIdx.x * 32, c0 = blockIdx.y * 32;
    const int tx = threadIdx.x & 31, ty = threadIdx.x >> 5;   // 32 x 8
    #pragma unroll
    for (int i = ty; i < 32; i += 8)
        tile[i][tx] = src[(size_t)(c0 + i) * NPIX + n0 + tx];
    __syncthreads();
    #pragma unroll
    for (int i = ty; i < 32; i += 8)
        dst[(size_t)(n0 + i) * C + c0 + tx] = tile[tx][i];
}

// ---------------- rowsum reduce: partial[64][B*N] -> rowsum[B*N] ----------------
__global__ __launch_bounds__(256) void reduce_rowsum_k() {
    const int idx = blockIdx.x * 256 + threadIdx.x;           // < BATCH*NPIX
    float s = 0.f;
    #pragma unroll
    for (int i = 0; i < 64; i++)
        s += g_partial[(size_t)i * (BATCH * NPIX) + idx];
    g_rowsum[idx] = s;
}

// ---------------- fp16 tensor GEMM via mma.sync (m16n8k16) ----------------
// D[m,n] = sum_k A[m,k] * B[n,k]; epilogue by MODE:
//   0: fp32 out + bias      (out-proj)
//   1: half out + bias      (qkv)
//   2: half out = exp(D/16 - EXP_SHIFT), write per-row partial sums  (scores)
//   3: half out = D / rowsum[row]                                    (PV)
// Block tile 128x128, KTILE=32 halves, 8 warps (4m x 2n), warp tile 32x64.
#define HKT  32
#define HSTR 40
#define HSTG (128 * HSTR)                   // halves per stage per operand

template<int MODE>
__global__ __launch_bounds__(256)
void hgemm_k(const __half* __restrict__ A, const __half* __restrict__ B,
             const float* __restrict__ bias, const float* __restrict__ aux,
             float* __restrict__ auxw, void* __restrict__ Cg,
             int lda, int ldb, int ldc, int K,
             long long sA, long long sB, long long sC)
{
    __shared__ __half sm[4 * HSTG];         // As0 Bs0 As1 Bs1 = 40960 B

    const int t = threadIdx.x, wid = t >> 5, lane = t & 31;
    const int g = lane >> 2, tq = lane & 3;
    const int wm = (wid >> 1) * 32;         // 4 warps along m
    const int wn = (wid & 1) * 64;          // 2 warps along n
    const int bm = blockIdx.y * 128;
    const int bn = blockIdx.x * 128;
    A += (long long)blockIdx.z * sA + (long long)bm * lda;
    B += (long long)blockIdx.z * sB + (long long)bn * ldb;

    const int lr = t >> 2;                  // load row (0..63), +64 per half
    const int lch = (t & 3) << 3;           // load col halves (0,8,16,24)

    float acc[2][8][4];
    #pragma unroll
    for (int i = 0; i < 2; i++)
        #pragma unroll
        for (int j = 0; j < 8; j++)
            #pragma unroll
            for (int r = 0; r < 4; r++) acc[i][j][r] = 0.f;

    uint4 ra[2], rb[2];

    // prologue: load k-tile 0
    #pragma unroll
    for (int i = 0; i < 2; i++) {
        ra[i] = *reinterpret_cast<const uint4*>(&A[(long long)(lr + 64 * i) * lda + lch]);
        rb[i] = *reinterpret_cast<const uint4*>(&B[(long long)(lr + 64 * i) * ldb + lch]);
    }
    #pragma unroll
    for (int i = 0; i < 2; i++) {
        *reinterpret_cast<uint4*>(&sm[(lr + 64 * i) * HSTR + lch])        = ra[i];
        *reinterpret_cast<uint4*>(&sm[HSTG + (lr + 64 * i) * HSTR + lch]) = rb[i];
    }
    __syncthreads();

    const int T = K / HKT;
    int buf = 0;
    for (int kt = 0; kt < T; kt++) {
        if (kt + 1 < T) {
            const int k0 = (kt + 1) * HKT;
            #pragma unroll
            for (int i = 0; i < 2; i++) {
                ra[i] = *reinterpret_cast<const uint4*>(&A[(long long)(lr + 64 * i) * lda + k0 + lch]);
                rb[i] = *reinterpret_cast<const uint4*>(&B[(long long)(lr + 64 * i) * ldb + k0 + lch]);
            }
        }

        // compute on buf
        {
            const __half* Ab = sm + buf * 2 * HSTG;
            const __half* Bb = Ab + HSTG;
            #pragma unroll
            for (int ks = 0; ks < HKT; ks += 16) {
                uint32_t af[2][4], bf[8][2];
                #pragma unroll
                for (int mf = 0; mf < 2; mf++) {
                    const int r0 = wm + mf * 16 + g;
                    af[mf][0] = *reinterpret_cast<const uint32_t*>(&Ab[r0 * HSTR + ks + 2 * tq]);
                    af[mf][1] = *reinterpret_cast<const uint32_t*>(&Ab[(r0 + 8) * HSTR + ks + 2 * tq]);
                    af[mf][2] = *reinterpret_cast<const uint32_t*>(&Ab[r0 * HSTR + ks + 2 * tq + 8]);
                    af[mf][3] = *reinterpret_cast<const uint32_t*>(&Ab[(r0 + 8) * HSTR + ks + 2 * tq + 8]);
                }
                #pragma unroll
                for (int nf = 0; nf < 8; nf++) {
                    const int n0 = wn + nf * 8 + g;
                    bf[nf][0] = *reinterpret_cast<const uint32_t*>(&Bb[n0 * HSTR + ks + 2 * tq]);
                    bf[nf][1] = *reinterpret_cast<const uint32_t*>(&Bb[n0 * HSTR + ks + 2 * tq + 8]);
                }
                #pragma unroll
                for (int mf = 0; mf < 2; mf++)
                    #pragma unroll
                    for (int nf = 0; nf < 8; nf++)
                        MMA_F16(acc[mf][nf], af[mf], bf[nf]);
            }
        }

        if (kt + 1 < T) {
            __half* Ab = sm + (buf ^ 1) * 2 * HSTG;
            __half* Bb = Ab + HSTG;
            #pragma unroll
            for (int i = 0; i < 2; i++) {
                *reinterpret_cast<uint4*>(&Ab[(lr + 64 * i) * HSTR + lch]) = ra[i];
                *reinterpret_cast<uint4*>(&Bb[(lr + 64 * i) * HSTR + lch]) = rb[i];
            }
        }
        __syncthreads();
        buf ^= 1;
    }

    // ---- epilogue ----
    float psum[2][2];
    if (MODE == 2) {
        psum[0][0] = psum[0][1] = psum[1][0] = psum[1][1] = 0.f;
        #pragma unroll
        for (int mf = 0; mf < 2; mf++)
            #pragma unroll
            for (int nf = 0; nf < 8; nf++)
                #pragma unroll
                for (int r = 0; r < 4; r++) {
                    const float e = __expf(fmaf(acc[mf][nf][r], 0.0625f, -EXP_SHIFT));
                    acc[mf][nf][r] = e;
                    psum[mf][r >> 1] += e;
                }
    }

    #pragma unroll
    for (int mf = 0; mf < 2; mf++)
        #pragma unroll
        for (int h = 0; h < 2; h++) {
            const long long row = bm + wm + mf * 16 + g + 8 * h;
            float bv = 0.f, scl = 1.f;
            if (MODE == 0 || MODE == 1) bv = __ldg(&bias[row]);
            if (MODE == 3) scl = 1.f / __ldg(&aux[(size_t)blockIdx.z * NPIX + row]);
            #pragma unroll
            for (int nf = 0; nf < 8; nf++) {
                const long long col = bn + wn + nf * 8 + 2 * tq;
                float vx = acc[mf][nf][2 * h];
                float vy = acc[mf][nf][2 * h + 1];
                if (MODE == 0 || MODE == 1) { vx += bv; vy += bv; }
                if (MODE == 3)              { vx *= scl; vy *= scl; }
                if (MODE == 0) {
                    float* Cf = (float*)Cg + (long long)blockIdx.z * sC;
                    *reinterpret_cast<float2*>(&Cf[row * ldc + col]) = make_float2(vx, vy);
                } else {
                    __half* Ch = (__half*)Cg + (long long)blockIdx.z * sC;
                    *reinterpret_cast<__half2*>(&Ch[row * ldc + col]) = __floats2half2_rn(vx, vy);
                }
            }
        }

    if (MODE == 2) {
        // reduce row partials across the 4 lanes of each quad (tq), then store
        #pragma unroll
        for (int mf = 0; mf < 2; mf++)
            #pragma unroll
            for (int h = 0; h < 2; h++) {
                float s = psum[mf][h];
                s += __shfl_xor_sync(0xffffffffu, s, 1);
                s += __shfl_xor_sync(0xffffffffu, s, 2);
                if (tq == 0) {
                    const int slot = blockIdx.x * 2 + (wid & 1);   // 64 slots
                    const long long row = bm + wm + mf * 16 + g + 8 * h;
                    auxw[(size_t)slot * (BATCH * NPIX) + (size_t)blockIdx.z * NPIX + row] = s;
                }
            }
    }
}

// ---------------- launch ----------------
extern "C" void kernel_launch(void* const* d_in, const int* in_sizes, int n_in,
                              void* d_out, int out_size) {
    (void)in_sizes; (void)n_in; (void)out_size;
    const float* x        = (const float*)d_in[0];
    const float* gn_gamma = (const float*)d_in[1];
    const float* gn_beta  = (const float*)d_in[2];
    const float* w_qkv    = (const float*)d_in[3];
    const float* b_qkv    = (const float*)d_in[4];
    const float* w_out    = (const float*)d_in[5];
    const float* b_out    = (const float*)d_in[6];
    float* out = (float*)d_out;

    __half *xnt, *qkvh, *qth, *kth, *ph, *oth, *wqh, *woh;
    float *partial, *rowsum;
    cudaGetSymbolAddress((void**)&xnt,     g_xnt);
    cudaGetSymbolAddress((void**)&qkvh,    g_qkvh);
    cudaGetSymbolAddress((void**)&qth,     g_qth);
    cudaGetSymbolAddress((void**)&kth,     g_kth);
    cudaGetSymbolAddress((void**)&ph,      g_ph);
    cudaGetSymbolAddress((void**)&oth,     g_oth);
    cudaGetSymbolAddress((void**)&wqh,     g_wqh);
    cudaGetSymbolAddress((void**)&woh,     g_woh);
    cudaGetSymbolAddress((void**)&partial, g_partial);
    cudaGetSymbolAddress((void**)&rowsum,  g_rowsum);

    // 1) group-norm stats; weight conversion (independent)
    gn_stats_k<<<BATCH * GROUPS, 256>>>(x);
    conv_w_k<<<256, 256>>>(w_qkv, w_out);

    // 2) GN apply + transpose -> xnT [n, c] half
    gn_apply_t_k<<<dim3(NPIX / 32, C / 32, BATCH), 256>>>(x, gn_gamma, gn_beta);

    // 3) qkv[o,n] half = Wqkv[o,c] . xnT[n,c]^T + b_qkv
    hgemm_k<1><<<dim3(NPIX / 128, (3 * C) / 128, BATCH), 256>>>(
        wqh, xnt, b_qkv, nullptr, nullptr, qkvh, C, C, NPIX, C,
        0LL, (long long)NPIX * C, (long long)3 * C * NPIX);

    // 4) transpose Q,K -> half [n,c]
    transpose_qk_k<<<dim3(NPIX / 32, C / 32, BATCH * 2), 256>>>();

    // 5) scores+exp: Ph[j,i] = exp(Qt[j].Kt[i]/16 - SHIFT); partial row sums
    hgemm_k<2><<<dim3(NPIX / 128, NPIX / 128, BATCH), 256>>>(
        qth, kth, nullptr, nullptr, partial, ph, C, C, NPIX, C,
        (long long)NPIX * C, (long long)NPIX * C, (long long)NPIX * NPIX);

    // 6) rowsum[b,j] = sum of 64 partials
    reduce_rowsum_k<<<BATCH * NPIX / 256, 256>>>();

    // 7) O^T[j,c] half = (Ph[j,:] . V[c,:]^T) / rowsum[b,j]   (K = 4096)
    hgemm_k<3><<<dim3(C / 128, NPIX / 128, BATCH), 256>>>(
        ph, qkvh + (size_t)2 * C * NPIX, nullptr, rowsum, nullptr, oth,
        NPIX, NPIX, C, NPIX,
        (long long)NPIX * NPIX, (long long)3 * C * NPIX, (long long)NPIX * C);

    // 8) out[o,j] fp32 = Wout[o,c] . OT[j,c]^T + b_out
    hgemm_k<0><<<dim3(NPIX / 128, C / 128, BATCH), 256>>>(
        woh, oth, b_out, nullptr, nullptr, out, C, C, NPIX, C,
        0LL, (long long)NPIX * C, (long long)C * NPIX);
}

// round 10
// speedup vs baseline: 5.0929x; 1.0980x over previous
#include <cuda_runtime.h>
#include <cuda_fp16.h>
#include <math.h>
#include <stdint.h>

// ---------------- problem constants ----------------
#define BATCH 4
#define C     256
#define NPIX  4096          // 64*64
#define GROUPS 32
#define GELEMS ((C/GROUPS)*NPIX)   // 32768 elements per group
#define EPSV  1e-5f
#define EXP_SHIFT 4.0f      // softmax fixed shift: e^(s-4); safe for s_max in (-inf, ~15]

// ---------------- scratch (device globals, no allocation) ----------------
__device__ __half g_xnt [(size_t)BATCH*NPIX*C];           // 8 MB   xn^T [n, c] half
__device__ __half g_qkvh[(size_t)BATCH*3*C*NPIX];         // 24 MB  qkv [o, n] half
__device__ __half g_qth [(size_t)BATCH*NPIX*C];           // 8 MB   Q^T [n, c] half
__device__ __half g_kth [(size_t)BATCH*NPIX*C];           // 8 MB   K^T [n, c] half
__device__ __half g_ph  [(size_t)BATCH*NPIX*NPIX];        // 128 MB unnormalized probs half
__device__ __half g_oth [(size_t)BATCH*NPIX*C];           // 8 MB   O^T [j, c] half
__device__ __half g_wqh [3*C*C];                          // W_qkv half
__device__ __half g_woh [C*C];                            // W_out half
__device__ float  g_partial[(size_t)64*BATCH*NPIX];       // 4 MB   per-(i-slot) row sums
__device__ float  g_rowsum [(size_t)BATCH*NPIX];          // 64 KB  softmax denominators
__device__ float  g_mu  [BATCH*GROUPS];
__device__ float  g_rstd[BATCH*GROUPS];

// ---------------- helpers ----------------
#define MMA_F16(d, a, b) \
    asm volatile("mma.sync.aligned.m16n8k16.row.col.f32.f16.f16.f32 " \
        "{%0,%1,%2,%3}, {%4,%5,%6,%7}, {%8,%9}, {%0,%1,%2,%3};" \
        : "+f"((d)[0]), "+f"((d)[1]), "+f"((d)[2]), "+f"((d)[3]) \
        : "r"((a)[0]), "r"((a)[1]), "r"((a)[2]), "r"((a)[3]), \
          "r"((b)[0]), "r"((b)[1]))

#define CPA16(dst, src) \
    asm volatile("cp.async.cg.shared.global [%0], [%1], 16;" :: "r"(dst), "l"(src))
#define CPA_COMMIT() asm volatile("cp.async.commit_group;" ::: "memory")
#define CPA_WAIT(n)  asm volatile("cp.async.wait_group %0;" :: "n"(n) : "memory")

__device__ __forceinline__ float warpRedSum(float v) {
    #pragma unroll
    for (int o = 16; o > 0; o >>= 1) v += __shfl_xor_sync(0xffffffffu, v, o);
    return v;
}

// ---------------- fused group-norm stats + weight conversion ----------------
__global__ __launch_bounds__(256) void gn_stats_convw_k(const float* __restrict__ x,
                                                        const float* __restrict__ wq,
                                                        const float* __restrict__ wo) {
    if (blockIdx.x >= BATCH * GROUPS) {
        // weight conversion blocks
        const int i4 = (blockIdx.x - BATCH * GROUPS) * 256 + threadIdx.x;  // < 65536
        const int WQ4 = 3 * C * C / 4;                                     // 49152
        float4 v;
        if (i4 < WQ4) v = reinterpret_cast<const float4*>(wq)[i4];
        else          v = reinterpret_cast<const float4*>(wo)[i4 - WQ4];
        __half2 h0 = __floats2half2_rn(v.x, v.y);
        __half2 h1 = __floats2half2_rn(v.z, v.w);
        __half* dst = (i4 < WQ4) ? (g_wqh + (size_t)i4 * 4) : (g_woh + (size_t)(i4 - WQ4) * 4);
        *reinterpret_cast<__half2*>(dst)     = h0;
        *reinterpret_cast<__half2*>(dst + 2) = h1;
        return;
    }
    const int bg = blockIdx.x;
    const float4* base = reinterpret_cast<const float4*>(x + (size_t)bg * GELEMS);
    float s = 0.f, ss = 0.f;
    for (int i = threadIdx.x; i < GELEMS / 4; i += 256) {
        float4 v = base[i];
        s  += v.x + v.y + v.z + v.w;
        ss += v.x*v.x + v.y*v.y + v.z*v.z + v.w*v.w;
    }
    __shared__ float shs[32], shss[32];
    float ws = warpRedSum(s), wss = warpRedSum(ss);
    const int lane = threadIdx.x & 31, wid = threadIdx.x >> 5;
    if (lane == 0) { shs[wid] = ws; shss[wid] = wss; }
    __syncthreads();
    if (wid == 0) {
        float a = (lane < 8) ? shs[lane] : 0.f;
        float b = (lane < 8) ? shss[lane] : 0.f;
        a = warpRedSum(a); b = warpRedSum(b);
        if (lane == 0) {
            float mean = a * (1.f / (float)GELEMS);
            float var  = b * (1.f / (float)GELEMS) - mean * mean;
            g_mu[bg] = mean;
            g_rstd[bg] = rsqrtf(var + EPSV);
        }
    }
}

// ---------------- group-norm apply + transpose: x[c,n] -> xnT[n,c] (half) ----------------
__global__ __launch_bounds__(256) void gn_apply_t_k(const float* __restrict__ x,
                                                    const float* __restrict__ gamma,
                                                    const float* __restrict__ beta) {
    const int b  = blockIdx.z;
    const int n0 = blockIdx.x * 32, c0 = blockIdx.y * 32;
    const float* src = x + (size_t)b * C * NPIX;
    __half* dst = g_xnt + (size_t)b * NPIX * C;
    __shared__ float tile[32][33];
    const int tx = threadIdx.x & 31, ty = threadIdx.x >> 5;   // 32 x 8
    #pragma unroll
    for (int i = ty; i < 32; i += 8) {
        const int c = c0 + i;
        const int bg = b * GROUPS + (c >> 3);                 // 8 channels per group
        const float sc = gamma[c] * g_rstd[bg];
        const float sh = beta[c] - g_mu[bg] * sc;
        tile[i][tx] = fmaf(src[(size_t)c * NPIX + n0 + tx], sc, sh);
    }
    __syncthreads();
    #pragma unroll
    for (int i = ty; i < 32; i += 8)
        dst[(size_t)(n0 + i) * C + c0 + tx] = __float2half_rn(tile[tx][i]);
}

// ---------------- transpose Q,K [C,N] half -> [N,C] half ----------------
__global__ __launch_bounds__(256) void transpose_qk_k() {
    const int which = blockIdx.z & 1;       // 0=Q, 1=K
    const int b     = blockIdx.z >> 1;
    const __half* src = g_qkvh + (size_t)b * 3 * C * NPIX + (size_t)which * C * NPIX;
    __half* dst = (which ? g_kth : g_qth) + (size_t)b * NPIX * C;
    __shared__ __half tile[32][34];
    const int n0 = blockIdx.x * 32, c0 = blockIdx.y * 32;
    const int tx = threadIdx.x & 31, ty = threadIdx.x >> 5;   // 32 x 8
    #pragma unroll
    for (int i = ty; i < 32; i += 8)
        tile[i][tx] = src[(size_t)(c0 + i) * NPIX + n0 + tx];
    __syncthreads();
    #pragma unroll
    for (int i = ty; i < 32; i += 8)
        dst[(size_t)(n0 + i) * C + c0 + tx] = tile[tx][i];
}

// ---------------- rowsum reduce: partial[64][B*N] -> rowsum[B*N] ----------------
__global__ __launch_bounds__(256) void reduce_rowsum_k() {
    const int idx = blockIdx.x * 256 + threadIdx.x;           // < BATCH*NPIX
    float s = 0.f;
    #pragma unroll
    for (int i = 0; i < 64; i++)
        s += g_partial[(size_t)i * (BATCH * NPIX) + idx];
    g_rowsum[idx] = s;
}

// ---------------- fp16 tensor GEMM, 4-stage cp.async pipeline ----------------
// D[m,n] = sum_k A[m,k] * B[n,k]; epilogue by MODE:
//   0: fp32 out + bias      (out-proj)
//   1: half out + bias      (qkv)
//   2: half out = exp(D/16 - EXP_SHIFT), write per-row partial sums  (scores)
//   3: half out = D / rowsum[row]                                    (PV)
// Block tile 128x128, KTILE=32 halves, 8 warps (4m x 2n), warp tile 32x64.
#define HKT    32
#define HSTR   40
#define A_H    (128 * HSTR)                 // halves per operand per stage (5120)
#define STG_H  (2 * A_H)                    // halves per stage (A+B)
#define STAGES 4
#define SMEM_BYTES (STAGES * STG_H * 2)     // 81920

template<int MODE>
__global__ __launch_bounds__(256)
void hgemm_k(const __half* __restrict__ A, const __half* __restrict__ B,
             const float* __restrict__ bias, const float* __restrict__ aux,
             float* __restrict__ auxw, void* __restrict__ Cg,
             int lda, int ldb, int ldc, int K,
             long long sA, long long sB, long long sC)
{
    extern __shared__ __half sm[];
    const uint32_t smem_b = (uint32_t)__cvta_generic_to_shared(sm);

    const int t = threadIdx.x, wid = t >> 5, lane = t & 31;
    const int g = lane >> 2, tq = lane & 3;
    const int wm = (wid >> 1) * 32;         // 4 warps along m
    const int wn = (wid & 1) * 64;          // 2 warps along n
    const int bm = blockIdx.y * 128;
    const int bn = blockIdx.x * 128;
    A += (long long)blockIdx.z * sA + (long long)bm * lda;
    B += (long long)blockIdx.z * sB + (long long)bn * ldb;

    const int lr = t >> 2;                  // load row (0..63), +64 per half
    const int lch = (t & 3) << 3;           // load col halves (0,8,16,24)
    const uint32_t d_a0 = smem_b + (uint32_t)(lr * HSTR + lch) * 2;
    const uint32_t d_b0 = d_a0 + A_H * 2;

    float acc[2][8][4];
    #pragma unroll
    for (int i = 0; i < 2; i++)
        #pragma unroll
        for (int j = 0; j < 8; j++)
            #pragma unroll
            for (int r = 0; r < 4; r++) acc[i][j][r] = 0.f;

    const int T = K / HKT;

    // prologue: issue stages 0..STAGES-2
    #pragma unroll
    for (int s = 0; s < STAGES - 1; s++) {
        const int k0 = s * HKT;
        const uint32_t off = (uint32_t)s * (STG_H * 2);
        #pragma unroll
        for (int i = 0; i < 2; i++) {
            CPA16(d_a0 + off + i * (64 * HSTR * 2), &A[(long long)(lr + 64 * i) * lda + k0 + lch]);
            CPA16(d_b0 + off + i * (64 * HSTR * 2), &B[(long long)(lr + 64 * i) * ldb + k0 + lch]);
        }
        CPA_COMMIT();
    }

    int slot = 0;
    for (int kt = 0; kt < T; kt++) {
        CPA_WAIT(STAGES - 2);               // stage kt's group has retired
        __syncthreads();

        // issue stage kt+STAGES-1 into slot (kt+STAGES-1)%STAGES (freed in iter kt-1)
        if (kt + STAGES - 1 < T) {
            const int k0 = (kt + STAGES - 1) * HKT;
            const int ws = (slot + STAGES - 1 >= STAGES) ? slot - 1 : slot + STAGES - 1;
            const uint32_t off = (uint32_t)ws * (STG_H * 2);
            #pragma unroll
            for (int i = 0; i < 2; i++) {
                CPA16(d_a0 + off + i * (64 * HSTR * 2), &A[(long long)(lr + 64 * i) * lda + k0 + lch]);
                CPA16(d_b0 + off + i * (64 * HSTR * 2), &B[(long long)(lr + 64 * i) * ldb + k0 + lch]);
            }
            CPA_COMMIT();
        }

        // compute on slot
        {
            const __half* Ab = sm + slot * STG_H;
            const __half* Bb = Ab + A_H;
            #pragma unroll
            for (int ks = 0; ks < HKT; ks += 16) {
                uint32_t af[2][4], bf[8][2];
                #pragma unroll
                for (int mf = 0; mf < 2; mf++) {
                    const int r0 = wm + mf * 16 + g;
                    af[mf][0] = *reinterpret_cast<const uint32_t*>(&Ab[r0 * HSTR + ks + 2 * tq]);
                    af[mf][1] = *reinterpret_cast<const uint32_t*>(&Ab[(r0 + 8) * HSTR + ks + 2 * tq]);
                    af[mf][2] = *reinterpret_cast<const uint32_t*>(&Ab[r0 * HSTR + ks + 2 * tq + 8]);
                    af[mf][3] = *reinterpret_cast<const uint32_t*>(&Ab[(r0 + 8) * HSTR + ks + 2 * tq + 8]);
                }
                #pragma unroll
                for (int nf = 0; nf < 8; nf++) {
                    const int n0 = wn + nf * 8 + g;
                    bf[nf][0] = *reinterpret_cast<const uint32_t*>(&Bb[n0 * HSTR + ks + 2 * tq]);
                    bf[nf][1] = *reinterpret_cast<const uint32_t*>(&Bb[n0 * HSTR + ks + 2 * tq + 8]);
                }
                #pragma unroll
                for (int mf = 0; mf < 2; mf++)
                    #pragma unroll
                    for (int nf = 0; nf < 8; nf++)
                        MMA_F16(acc[mf][nf], af[mf], bf[nf]);
            }
        }
        slot = (slot + 1 == STAGES) ? 0 : slot + 1;
    }

    // ---- epilogue ----
    float psum[2][2];
    if (MODE == 2) {
        psum[0][0] = psum[0][1] = psum[1][0] = psum[1][1] = 0.f;
        #pragma unroll
        for (int mf = 0; mf < 2; mf++)
            #pragma unroll
            for (int nf = 0; nf < 8; nf++)
                #pragma unroll
                for (int r = 0; r < 4; r++) {
                    const float e = __expf(fmaf(acc[mf][nf][r], 0.0625f, -EXP_SHIFT));
                    acc[mf][nf][r] = e;
                    psum[mf][r >> 1] += e;
                }
    }

    #pragma unroll
    for (int mf = 0; mf < 2; mf++)
        #pragma unroll
        for (int h = 0; h < 2; h++) {
            const long long row = bm + wm + mf * 16 + g + 8 * h;
            float bv = 0.f, scl = 1.f;
            if (MODE == 0 || MODE == 1) bv = __ldg(&bias[row]);
            if (MODE == 3) scl = 1.f / __ldg(&aux[(size_t)blockIdx.z * NPIX + row]);
            #pragma unroll
            for (int nf = 0; nf < 8; nf++) {
                const long long col = bn + wn + nf * 8 + 2 * tq;
                float vx = acc[mf][nf][2 * h];
                float vy = acc[mf][nf][2 * h + 1];
                if (MODE == 0 || MODE == 1) { vx += bv; vy += bv; }
                if (MODE == 3)              { vx *= scl; vy *= scl; }
                if (MODE == 0) {
                    float* Cf = (float*)Cg + (long long)blockIdx.z * sC;
                    *reinterpret_cast<float2*>(&Cf[row * ldc + col]) = make_float2(vx, vy);
                } else {
                    __half* Ch = (__half*)Cg + (long long)blockIdx.z * sC;
                    *reinterpret_cast<__half2*>(&Ch[row * ldc + col]) = __floats2half2_rn(vx, vy);
                }
            }
        }

    if (MODE == 2) {
        #pragma unroll
        for (int mf = 0; mf < 2; mf++)
            #pragma unroll
            for (int h = 0; h < 2; h++) {
                float s = psum[mf][h];
                s += __shfl_xor_sync(0xffffffffu, s, 1);
                s += __shfl_xor_sync(0xffffffffu, s, 2);
                if (tq == 0) {
                    const int slot2 = blockIdx.x * 2 + (wid & 1);   // 64 slots
                    const long long row = bm + wm + mf * 16 + g + 8 * h;
                    auxw[(size_t)slot2 * (BATCH * NPIX) + (size_t)blockIdx.z * NPIX + row] = s;
                }
            }
    }
}

// ---------------- launch ----------------
extern "C" void kernel_launch(void* const* d_in, const int* in_sizes, int n_in,
                              void* d_out, int out_size) {
    (void)in_sizes; (void)n_in; (void)out_size;
    const float* x        = (const float*)d_in[0];
    const float* gn_gamma = (const float*)d_in[1];
    const float* gn_beta  = (const float*)d_in[2];
    const float* w_qkv    = (const float*)d_in[3];
    const float* b_qkv    = (const float*)d_in[4];
    const float* w_out    = (const float*)d_in[5];
    const float* b_out    = (const float*)d_in[6];
    float* out = (float*)d_out;

    __half *xnt, *qkvh, *qth, *kth, *ph, *oth, *wqh, *woh;
    float *partial, *rowsum;
    cudaGetSymbolAddress((void**)&xnt,     g_xnt);
    cudaGetSymbolAddress((void**)&qkvh,    g_qkvh);
    cudaGetSymbolAddress((void**)&qth,     g_qth);
    cudaGetSymbolAddress((void**)&kth,     g_kth);
    cudaGetSymbolAddress((void**)&ph,      g_ph);
    cudaGetSymbolAddress((void**)&oth,     g_oth);
    cudaGetSymbolAddress((void**)&wqh,     g_wqh);
    cudaGetSymbolAddress((void**)&woh,     g_woh);
    cudaGetSymbolAddress((void**)&partial, g_partial);
    cudaGetSymbolAddress((void**)&rowsum,  g_rowsum);

    cudaFuncSetAttribute(hgemm_k<0>, cudaFuncAttributeMaxDynamicSharedMemorySize, SMEM_BYTES);
    cudaFuncSetAttribute(hgemm_k<1>, cudaFuncAttributeMaxDynamicSharedMemorySize, SMEM_BYTES);
    cudaFuncSetAttribute(hgemm_k<2>, cudaFuncAttributeMaxDynamicSharedMemorySize, SMEM_BYTES);
    cudaFuncSetAttribute(hgemm_k<3>, cudaFuncAttributeMaxDynamicSharedMemorySize, SMEM_BYTES);

    // 1) group-norm stats + weight conversion (fused launch)
    gn_stats_convw_k<<<BATCH * GROUPS + 256, 256>>>(x, w_qkv, w_out);

    // 2) GN apply + transpose -> xnT [n, c] half
    gn_apply_t_k<<<dim3(NPIX / 32, C / 32, BATCH), 256>>>(x, gn_gamma, gn_beta);

    // 3) qkv[o,n] half = Wqkv[o,c] . xnT[n,c]^T + b_qkv
    hgemm_k<1><<<dim3(NPIX / 128, (3 * C) / 128, BATCH), 256, SMEM_BYTES>>>(
        wqh, xnt, b_qkv, nullptr, nullptr, qkvh, C, C, NPIX, C,
        0LL, (long long)NPIX * C, (long long)3 * C * NPIX);

    // 4) transpose Q,K -> half [n,c]
    transpose_qk_k<<<dim3(NPIX / 32, C / 32, BATCH * 2), 256>>>();

    // 5) scores+exp: Ph[j,i] = exp(Qt[j].Kt[i]/16 - SHIFT); partial row sums
    hgemm_k<2><<<dim3(NPIX / 128, NPIX / 128, BATCH), 256, SMEM_BYTES>>>(
        qth, kth, nullptr, nullptr, partial, ph, C, C, NPIX, C,
        (long long)NPIX * C, (long long)NPIX * C, (long long)NPIX * NPIX);

    // 6) rowsum[b,j] = sum of 64 partials
    reduce_rowsum_k<<<BATCH * NPIX / 256, 256>>>();

    // 7) O^T[j,c] half = (Ph[j,:] . V[c,:]^T) / rowsum[b,j]   (K = 4096)
    hgemm_k<3><<<dim3(C / 128, NPIX / 128, BATCH), 256, SMEM_BYTES>>>(
        ph, qkvh + (size_t)2 * C * NPIX, nullptr, rowsum, nullptr, oth,
        NPIX, NPIX, C, NPIX,
        (long long)NPIX * NPIX, (long long)3 * C * NPIX, (long long)NPIX * C);

    // 8) out[o,j] fp32 = Wout[o,c] . OT[j,c]^T + b_out
    hgemm_k<0><<<dim3(NPIX / 128, C / 128, BATCH), 256, SMEM_BYTES>>>(
        woh, oth, b_out, nullptr, nullptr, out, C, C, NPIX, C,
        0LL, (long long)NPIX * C, (long long)C * NPIX);
}

// round 11
// speedup vs baseline: 5.6090x; 1.1013x over previous
#include <cuda_runtime.h>
#include <cuda_fp16.h>
#include <math.h>
#include <stdint.h>

// ---------------- problem constants ----------------
#define BATCH 4
#define C     256
#define NPIX  4096          // 64*64
#define GROUPS 32
#define GELEMS ((C/GROUPS)*NPIX)   // 32768 elements per group
#define EPSV  1e-5f
#define EXP_SHIFT 4.0f      // softmax fixed shift: e^(s-4); safe for s_max in (-inf, ~15]

// ---------------- scratch (device globals, no allocation) ----------------
__device__ __half g_xnt [(size_t)BATCH*NPIX*C];           // 8 MB   xn^T [n, c] half
__device__ __half g_qkvh[(size_t)BATCH*3*C*NPIX];         // 24 MB  qkv [o, n] half
__device__ __half g_qth [(size_t)BATCH*NPIX*C];           // 8 MB   Q^T [n, c] half
__device__ __half g_kth [(size_t)BATCH*NPIX*C];           // 8 MB   K^T [n, c] half
__device__ __half g_ph  [(size_t)BATCH*NPIX*NPIX];        // 128 MB unnormalized probs half
__device__ __half g_oth [(size_t)BATCH*NPIX*C];           // 8 MB   O^T [j, c] half
__device__ __half g_wqh [3*C*C];                          // W_qkv half
__device__ __half g_woh [C*C];                            // W_out half
__device__ float  g_partial[(size_t)64*BATCH*NPIX];       // 4 MB   per-(i-slot) row sums
__device__ float  g_rowsum [(size_t)BATCH*NPIX];          // 64 KB  softmax denominators
__device__ float  g_mu  [BATCH*GROUPS];
__device__ float  g_rstd[BATCH*GROUPS];

// ---------------- helpers ----------------
#define MMA_F16(d, a, b) \
    asm volatile("mma.sync.aligned.m16n8k16.row.col.f32.f16.f16.f32 " \
        "{%0,%1,%2,%3}, {%4,%5,%6,%7}, {%8,%9}, {%0,%1,%2,%3};" \
        : "+f"((d)[0]), "+f"((d)[1]), "+f"((d)[2]), "+f"((d)[3]) \
        : "r"((a)[0]), "r"((a)[1]), "r"((a)[2]), "r"((a)[3]), \
          "r"((b)[0]), "r"((b)[1]))

#define LDSM_X4(r0, r1, r2, r3, addr) \
    asm volatile("ldmatrix.sync.aligned.m8n8.x4.shared.b16 {%0,%1,%2,%3}, [%4];" \
        : "=r"(r0), "=r"(r1), "=r"(r2), "=r"(r3) : "r"(addr))

#define CPA16(dst, src) \
    asm volatile("cp.async.cg.shared.global [%0], [%1], 16;" :: "r"(dst), "l"(src))
#define CPA_COMMIT() asm volatile("cp.async.commit_group;" ::: "memory")
#define CPA_WAIT(n)  asm volatile("cp.async.wait_group %0;" :: "n"(n) : "memory")

__device__ __forceinline__ float warpRedSum(float v) {
    #pragma unroll
    for (int o = 16; o > 0; o >>= 1) v += __shfl_xor_sync(0xffffffffu, v, o);
    return v;
}

// ---------------- fused group-norm stats + weight conversion ----------------
__global__ __launch_bounds__(256) void gn_stats_convw_k(const float* __restrict__ x,
                                                        const float* __restrict__ wq,
                                                        const float* __restrict__ wo) {
    if (blockIdx.x >= BATCH * GROUPS) {
        const int i4 = (blockIdx.x - BATCH * GROUPS) * 256 + threadIdx.x;  // < 65536
        const int WQ4 = 3 * C * C / 4;                                     // 49152
        float4 v;
        if (i4 < WQ4) v = reinterpret_cast<const float4*>(wq)[i4];
        else          v = reinterpret_cast<const float4*>(wo)[i4 - WQ4];
        __half2 h0 = __floats2half2_rn(v.x, v.y);
        __half2 h1 = __floats2half2_rn(v.z, v.w);
        __half* dst = (i4 < WQ4) ? (g_wqh + (size_t)i4 * 4) : (g_woh + (size_t)(i4 - WQ4) * 4);
        *reinterpret_cast<__half2*>(dst)     = h0;
        *reinterpret_cast<__half2*>(dst + 2) = h1;
        return;
    }
    const int bg = blockIdx.x;
    const float4* base = reinterpret_cast<const float4*>(x + (size_t)bg * GELEMS);
    float s = 0.f, ss = 0.f;
    for (int i = threadIdx.x; i < GELEMS / 4; i += 256) {
        float4 v = base[i];
        s  += v.x + v.y + v.z + v.w;
        ss += v.x*v.x + v.y*v.y + v.z*v.z + v.w*v.w;
    }
    __shared__ float shs[32], shss[32];
    float ws = warpRedSum(s), wss = warpRedSum(ss);
    const int lane = threadIdx.x & 31, wid = threadIdx.x >> 5;
    if (lane == 0) { shs[wid] = ws; shss[wid] = wss; }
    __syncthreads();
    if (wid == 0) {
        float a = (lane < 8) ? shs[lane] : 0.f;
        float b = (lane < 8) ? shss[lane] : 0.f;
        a = warpRedSum(a); b = warpRedSum(b);
        if (lane == 0) {
            float mean = a * (1.f / (float)GELEMS);
            float var  = b * (1.f / (float)GELEMS) - mean * mean;
            g_mu[bg] = mean;
            g_rstd[bg] = rsqrtf(var + EPSV);
        }
    }
}

// ---------------- group-norm apply + transpose: x[c,n] -> xnT[n,c] (half) ----------------
__global__ __launch_bounds__(256) void gn_apply_t_k(const float* __restrict__ x,
                                                    const float* __restrict__ gamma,
                                                    const float* __restrict__ beta) {
    const int b  = blockIdx.z;
    const int n0 = blockIdx.x * 32, c0 = blockIdx.y * 32;
    const float* src = x + (size_t)b * C * NPIX;
    __half* dst = g_xnt + (size_t)b * NPIX * C;
    __shared__ float tile[32][33];
    const int tx = threadIdx.x & 31, ty = threadIdx.x >> 5;   // 32 x 8
    #pragma unroll
    for (int i = ty; i < 32; i += 8) {
        const int c = c0 + i;
        const int bg = b * GROUPS + (c >> 3);                 // 8 channels per group
        const float sc = gamma[c] * g_rstd[bg];
        const float sh = beta[c] - g_mu[bg] * sc;
        tile[i][tx] = fmaf(src[(size_t)c * NPIX + n0 + tx], sc, sh);
    }
    __syncthreads();
    #pragma unroll
    for (int i = ty; i < 32; i += 8)
        dst[(size_t)(n0 + i) * C + c0 + tx] = __float2half_rn(tile[tx][i]);
}

// ---------------- transpose Q,K [C,N] half -> [N,C] half ----------------
__global__ __launch_bounds__(256) void transpose_qk_k() {
    const int which = blockIdx.z & 1;       // 0=Q, 1=K
    const int b     = blockIdx.z >> 1;
    const __half* src = g_qkvh + (size_t)b * 3 * C * NPIX + (size_t)which * C * NPIX;
    __half* dst = (which ? g_kth : g_qth) + (size_t)b * NPIX * C;
    __shared__ __half tile[32][34];
    const int n0 = blockIdx.x * 32, c0 = blockIdx.y * 32;
    const int tx = threadIdx.x & 31, ty = threadIdx.x >> 5;   // 32 x 8
    #pragma unroll
    for (int i = ty; i < 32; i += 8)
        tile[i][tx] = src[(size_t)(c0 + i) * NPIX + n0 + tx];
    __syncthreads();
    #pragma unroll
    for (int i = ty; i < 32; i += 8)
        dst[(size_t)(n0 + i) * C + c0 + tx] = tile[tx][i];
}

// ---------------- rowsum reduce: partial[64][B*N] -> rowsum[B*N] ----------------
__global__ __launch_bounds__(256) void reduce_rowsum_k() {
    const int idx = blockIdx.x * 256 + threadIdx.x;           // < BATCH*NPIX
    float s = 0.f;
    #pragma unroll
    for (int i = 0; i < 64; i++)
        s += g_partial[(size_t)i * (BATCH * NPIX) + idx];
    g_rowsum[idx] = s;
}

// ---------------- fp16 tensor GEMM, 4-stage cp.async pipeline + ldmatrix ----------------
// D[m,n] = sum_k A[m,k] * B[n,k]; epilogue by MODE:
//   0: fp32 out + bias      (out-proj)
//   1: half out + bias      (qkv)
//   2: half out = exp(D/16 - EXP_SHIFT), write per-row partial sums  (scores)
//   3: half out = D / rowsum[row]                                    (PV)
// Block tile 128x128, KTILE=32 halves, 8 warps (4m x 2n), warp tile 32x64.
#define HKT    32
#define HSTR   40
#define A_H    (128 * HSTR)                 // halves per operand per stage (5120)
#define STG_H  (2 * A_H)                    // halves per stage (A+B)
#define STAGES 4
#define SMEM_BYTES (STAGES * STG_H * 2)     // 81920

template<int MODE>
__global__ __launch_bounds__(256)
void hgemm_k(const __half* __restrict__ A, const __half* __restrict__ B,
             const float* __restrict__ bias, const float* __restrict__ aux,
             float* __restrict__ auxw, void* __restrict__ Cg,
             int lda, int ldb, int ldc, int K,
             long long sA, long long sB, long long sC)
{
    extern __shared__ __half sm[];
    const uint32_t smem_b = (uint32_t)__cvta_generic_to_shared(sm);

    const int t = threadIdx.x, wid = t >> 5, lane = t & 31;
    const int g = lane >> 2, tq = lane & 3;
    const int wm = (wid >> 1) * 32;         // 4 warps along m
    const int wn = (wid & 1) * 64;          // 2 warps along n
    const int bm = blockIdx.y * 128;
    const int bn = blockIdx.x * 128;
    A += (long long)blockIdx.z * sA + (long long)bm * lda;
    B += (long long)blockIdx.z * sB + (long long)bn * ldb;

    const int lr = t >> 2;                  // load row (0..63), +64 per half
    const int lch = (t & 3) << 3;           // load col halves (0,8,16,24)
    const uint32_t d_a0 = smem_b + (uint32_t)(lr * HSTR + lch) * 2;
    const uint32_t d_b0 = d_a0 + A_H * 2;

    // ldmatrix per-lane byte offsets (within a stage)
    // A, mf in {0,1}: 4 tiles = rows (L&15), k-half (L>>4)*8
    uint32_t a_off[2], b_off[4];
    #pragma unroll
    for (int mf = 0; mf < 2; mf++)
        a_off[mf] = (uint32_t)(((wm + mf * 16 + (lane & 15)) * HSTR + ((lane >> 4) * 8)) * 2);
    // B, nf-pair p in {0..3}: 4 tiles = n rows p*16 + ((L&16)?8:0) + (L&7), k-half (L&8)?8:0
    #pragma unroll
    for (int p = 0; p < 4; p++)
        b_off[p] = (uint32_t)(((wn + p * 16 + ((lane & 16) ? 8 : 0) + (lane & 7)) * HSTR
                               + ((lane & 8) ? 8 : 0)) * 2) + A_H * 2;

    float acc[2][8][4];
    #pragma unroll
    for (int i = 0; i < 2; i++)
        #pragma unroll
        for (int j = 0; j < 8; j++)
            #pragma unroll
            for (int r = 0; r < 4; r++) acc[i][j][r] = 0.f;

    const int T = K / HKT;

    // prologue: issue stages 0..STAGES-2
    #pragma unroll
    for (int s = 0; s < STAGES - 1; s++) {
        const int k0 = s * HKT;
        const uint32_t off = (uint32_t)s * (STG_H * 2);
        #pragma unroll
        for (int i = 0; i < 2; i++) {
            CPA16(d_a0 + off + i * (64 * HSTR * 2), &A[(long long)(lr + 64 * i) * lda + k0 + lch]);
            CPA16(d_b0 + off + i * (64 * HSTR * 2), &B[(long long)(lr + 64 * i) * ldb + k0 + lch]);
        }
        CPA_COMMIT();
    }

    int slot = 0;
    for (int kt = 0; kt < T; kt++) {
        CPA_WAIT(STAGES - 2);               // stage kt's group has retired
        __syncthreads();

        // issue stage kt+STAGES-1 into slot (kt+STAGES-1)%STAGES (freed in iter kt-1)
        if (kt + STAGES - 1 < T) {
            const int k0 = (kt + STAGES - 1) * HKT;
            const int ws = (slot + STAGES - 1 >= STAGES) ? slot - 1 : slot + STAGES - 1;
            const uint32_t off = (uint32_t)ws * (STG_H * 2);
            #pragma unroll
            for (int i = 0; i < 2; i++) {
                CPA16(d_a0 + off + i * (64 * HSTR * 2), &A[(long long)(lr + 64 * i) * lda + k0 + lch]);
                CPA16(d_b0 + off + i * (64 * HSTR * 2), &B[(long long)(lr + 64 * i) * ldb + k0 + lch]);
            }
            CPA_COMMIT();
        }

        // compute on slot (ldmatrix fragment loads)
        {
            const uint32_t sbase = smem_b + (uint32_t)slot * (STG_H * 2);
            #pragma unroll
            for (int ks = 0; ks < HKT; ks += 16) {
                uint32_t af[2][4], bf[8][2];
                #pragma unroll
                for (int mf = 0; mf < 2; mf++)
                    LDSM_X4(af[mf][0], af[mf][1], af[mf][2], af[mf][3],
                            sbase + a_off[mf] + ks * 2);
                #pragma unroll
                for (int p = 0; p < 4; p++)
                    LDSM_X4(bf[2 * p][0], bf[2 * p][1], bf[2 * p + 1][0], bf[2 * p + 1][1],
                            sbase + b_off[p] + ks * 2);
                #pragma unroll
                for (int mf = 0; mf < 2; mf++)
                    #pragma unroll
                    for (int nf = 0; nf < 8; nf++)
                        MMA_F16(acc[mf][nf], af[mf], bf[nf]);
            }
        }
        slot = (slot + 1 == STAGES) ? 0 : slot + 1;
    }

    // ---- epilogue ----
    float psum[2][2];
    if (MODE == 2) {
        psum[0][0] = psum[0][1] = psum[1][0] = psum[1][1] = 0.f;
        #pragma unroll
        for (int mf = 0; mf < 2; mf++)
            #pragma unroll
            for (int nf = 0; nf < 8; nf++)
                #pragma unroll
                for (int r = 0; r < 4; r++) {
                    const float e = __expf(fmaf(acc[mf][nf][r], 0.0625f, -EXP_SHIFT));
                    acc[mf][nf][r] = e;
                    psum[mf][r >> 1] += e;
                }
    }

    #pragma unroll
    for (int mf = 0; mf < 2; mf++)
        #pragma unroll
        for (int h = 0; h < 2; h++) {
            const long long row = bm + wm + mf * 16 + g + 8 * h;
            float bv = 0.f, scl = 1.f;
            if (MODE == 0 || MODE == 1) bv = __ldg(&bias[row]);
            if (MODE == 3) scl = 1.f / __ldg(&aux[(size_t)blockIdx.z * NPIX + row]);
            #pragma unroll
            for (int nf = 0; nf < 8; nf++) {
                const long long col = bn + wn + nf * 8 + 2 * tq;
                float vx = acc[mf][nf][2 * h];
                float vy = acc[mf][nf][2 * h + 1];
                if (MODE == 0 || MODE == 1) { vx += bv; vy += bv; }
                if (MODE == 3)              { vx *= scl; vy *= scl; }
                if (MODE == 0) {
                    float* Cf = (float*)Cg + (long long)blockIdx.z * sC;
                    *reinterpret_cast<float2*>(&Cf[row * ldc + col]) = make_float2(vx, vy);
                } else {
                    __half* Ch = (__half*)Cg + (long long)blockIdx.z * sC;
                    *reinterpret_cast<__half2*>(&Ch[row * ldc + col]) = __floats2half2_rn(vx, vy);
                }
            }
        }

    if (MODE == 2) {
        #pragma unroll
        for (int mf = 0; mf < 2; mf++)
            #pragma unroll
            for (int h = 0; h < 2; h++) {
                float s = psum[mf][h];
                s += __shfl_xor_sync(0xffffffffu, s, 1);
                s += __shfl_xor_sync(0xffffffffu, s, 2);
                if (tq == 0) {
                    const int slot2 = blockIdx.x * 2 + (wid & 1);   // 64 slots
                    const long long row = bm + wm + mf * 16 + g + 8 * h;
                    auxw[(size_t)slot2 * (BATCH * NPIX) + (size_t)blockIdx.z * NPIX + row] = s;
                }
            }
    }
}

// ---------------- launch ----------------
extern "C" void kernel_launch(void* const* d_in, const int* in_sizes, int n_in,
                              void* d_out, int out_size) {
    (void)in_sizes; (void)n_in; (void)out_size;
    const float* x        = (const float*)d_in[0];
    const float* gn_gamma = (const float*)d_in[1];
    const float* gn_beta  = (const float*)d_in[2];
    const float* w_qkv    = (const float*)d_in[3];
    const float* b_qkv    = (const float*)d_in[4];
    const float* w_out    = (const float*)d_in[5];
    const float* b_out    = (const float*)d_in[6];
    float* out = (float*)d_out;

    __half *xnt, *qkvh, *qth, *kth, *ph, *oth, *wqh, *woh;
    float *partial, *rowsum;
    cudaGetSymbolAddress((void**)&xnt,     g_xnt);
    cudaGetSymbolAddress((void**)&qkvh,    g_qkvh);
    cudaGetSymbolAddress((void**)&qth,     g_qth);
    cudaGetSymbolAddress((void**)&kth,     g_kth);
    cudaGetSymbolAddress((void**)&ph,      g_ph);
    cudaGetSymbolAddress((void**)&oth,     g_oth);
    cudaGetSymbolAddress((void**)&wqh,     g_wqh);
    cudaGetSymbolAddress((void**)&woh,     g_woh);
    cudaGetSymbolAddress((void**)&partial, g_partial);
    cudaGetSymbolAddress((void**)&rowsum,  g_rowsum);

    cudaFuncSetAttribute(hgemm_k<0>, cudaFuncAttributeMaxDynamicSharedMemorySize, SMEM_BYTES);
    cudaFuncSetAttribute(hgemm_k<1>, cudaFuncAttributeMaxDynamicSharedMemorySize, SMEM_BYTES);
    cudaFuncSetAttribute(hgemm_k<2>, cudaFuncAttributeMaxDynamicSharedMemorySize, SMEM_BYTES);
    cudaFuncSetAttribute(hgemm_k<3>, cudaFuncAttributeMaxDynamicSharedMemorySize, SMEM_BYTES);

    // 1) group-norm stats + weight conversion (fused launch)
    gn_stats_convw_k<<<BATCH * GROUPS + 256, 256>>>(x, w_qkv, w_out);

    // 2) GN apply + transpose -> xnT [n, c] half
    gn_apply_t_k<<<dim3(NPIX / 32, C / 32, BATCH), 256>>>(x, gn_gamma, gn_beta);

    // 3) qkv[o,n] half = Wqkv[o,c] . xnT[n,c]^T + b_qkv
    hgemm_k<1><<<dim3(NPIX / 128, (3 * C) / 128, BATCH), 256, SMEM_BYTES>>>(
        wqh, xnt, b_qkv, nullptr, nullptr, qkvh, C, C, NPIX, C,
        0LL, (long long)NPIX * C, (long long)3 * C * NPIX);

    // 4) transpose Q,K -> half [n,c]
    transpose_qk_k<<<dim3(NPIX / 32, C / 32, BATCH * 2), 256>>>();

    // 5) scores+exp: Ph[j,i] = exp(Qt[j].Kt[i]/16 - SHIFT); partial row sums
    hgemm_k<2><<<dim3(NPIX / 128, NPIX / 128, BATCH), 256, SMEM_BYTES>>>(
        qth, kth, nullptr, nullptr, partial, ph, C, C, NPIX, C,
        (long long)NPIX * C, (long long)NPIX * C, (long long)NPIX * NPIX);

    // 6) rowsum[b,j] = sum of 64 partials
    reduce_rowsum_k<<<BATCH * NPIX / 256, 256>>>();

    // 7) O^T[j,c] half = (Ph[j,:] . V[c,:]^T) / rowsum[b,j]   (K = 4096)
    hgemm_k<3><<<dim3(C / 128, NPIX / 128, BATCH), 256, SMEM_BYTES>>>(
        ph, qkvh + (size_t)2 * C * NPIX, nullptr, rowsum, nullptr, oth,
        NPIX, NPIX, C, NPIX,
        (long long)NPIX * NPIX, (long long)3 * C * NPIX, (long long)NPIX * C);

    // 8) out[o,j] fp32 = Wout[o,c] . OT[j,c]^T + b_out
    hgemm_k<0><<<dim3(NPIX / 128, C / 128, BATCH), 256, SMEM_BYTES>>>(
        woh, oth, b_out, nullptr, nullptr, out, C, C, NPIX, C,
        0LL, (long long)NPIX * C, (long long)C * NPIX);
}

// round 12
// speedup vs baseline: 5.7372x; 1.0229x over previous
#include <cuda_runtime.h>
#include <cuda_fp16.h>
#include <math.h>
#include <stdint.h>

// ---------------- problem constants ----------------
#define BATCH 4
#define C     256
#define NPIX  4096          // 64*64
#define GROUPS 32
#define GELEMS ((C/GROUPS)*NPIX)   // 32768 elements per group
#define EPSV  1e-5f
#define EXP_SHIFT 4.0f      // softmax fixed shift: e^(s-4); safe for s_max in (-inf, ~15]

// ---------------- scratch (device globals, no allocation) ----------------
__device__ __half g_xnh [(size_t)BATCH*C*NPIX];           // 8 MB   xn [c, n] half
__device__ __half g_qkvh[(size_t)BATCH*3*C*NPIX];         // 24 MB  qkv [o, n] half
__device__ __half g_ph  [(size_t)BATCH*NPIX*NPIX];        // 128 MB unnormalized probs half
__device__ __half g_oth [(size_t)BATCH*NPIX*C];           // 8 MB   O^T [j, c] half
__device__ __half g_wqh [3*C*C];                          // W_qkv half
__device__ __half g_woh [C*C];                            // W_out half
__device__ float  g_partial[(size_t)64*BATCH*NPIX];       // 4 MB   per-(i-slot) row sums
__device__ float  g_rowsum [(size_t)BATCH*NPIX];          // 64 KB  softmax denominators
__device__ float  g_mu  [BATCH*GROUPS];
__device__ float  g_rstd[BATCH*GROUPS];

// ---------------- helpers ----------------
#define MMA_F16(d, a, b) \
    asm volatile("mma.sync.aligned.m16n8k16.row.col.f32.f16.f16.f32 " \
        "{%0,%1,%2,%3}, {%4,%5,%6,%7}, {%8,%9}, {%0,%1,%2,%3};" \
        : "+f"((d)[0]), "+f"((d)[1]), "+f"((d)[2]), "+f"((d)[3]) \
        : "r"((a)[0]), "r"((a)[1]), "r"((a)[2]), "r"((a)[3]), \
          "r"((b)[0]), "r"((b)[1]))

#define LDSM_X4(r0, r1, r2, r3, addr) \
    asm volatile("ldmatrix.sync.aligned.m8n8.x4.shared.b16 {%0,%1,%2,%3}, [%4];" \
        : "=r"(r0), "=r"(r1), "=r"(r2), "=r"(r3) : "r"(addr))

#define LDSM_X4_T(r0, r1, r2, r3, addr) \
    asm volatile("ldmatrix.sync.aligned.m8n8.x4.trans.shared.b16 {%0,%1,%2,%3}, [%4];" \
        : "=r"(r0), "=r"(r1), "=r"(r2), "=r"(r3) : "r"(addr))

#define CPA16(dst, src) \
    asm volatile("cp.async.cg.shared.global [%0], [%1], 16;" :: "r"(dst), "l"(src))
#define CPA_COMMIT() asm volatile("cp.async.commit_group;" ::: "memory")
#define CPA_WAIT(n)  asm volatile("cp.async.wait_group %0;" :: "n"(n) : "memory")

__device__ __forceinline__ float warpRedSum(float v) {
    #pragma unroll
    for (int o = 16; o > 0; o >>= 1) v += __shfl_xor_sync(0xffffffffu, v, o);
    return v;
}

// ---------------- fused group-norm stats + weight conversion ----------------
__global__ __launch_bounds__(256) void gn_stats_convw_k(const float* __restrict__ x,
                                                        const float* __restrict__ wq,
                                                        const float* __restrict__ wo) {
    if (blockIdx.x >= BATCH * GROUPS) {
        const int i4 = (blockIdx.x - BATCH * GROUPS) * 256 + threadIdx.x;  // < 65536
        const int WQ4 = 3 * C * C / 4;                                     // 49152
        float4 v;
        if (i4 < WQ4) v = reinterpret_cast<const float4*>(wq)[i4];
        else          v = reinterpret_cast<const float4*>(wo)[i4 - WQ4];
        __half2 h0 = __floats2half2_rn(v.x, v.y);
        __half2 h1 = __floats2half2_rn(v.z, v.w);
        __half* dst = (i4 < WQ4) ? (g_wqh + (size_t)i4 * 4) : (g_woh + (size_t)(i4 - WQ4) * 4);
        *reinterpret_cast<__half2*>(dst)     = h0;
        *reinterpret_cast<__half2*>(dst + 2) = h1;
        return;
    }
    const int bg = blockIdx.x;
    const float4* base = reinterpret_cast<const float4*>(x + (size_t)bg * GELEMS);
    float s = 0.f, ss = 0.f;
    for (int i = threadIdx.x; i < GELEMS / 4; i += 256) {
        float4 v = base[i];
        s  += v.x + v.y + v.z + v.w;
        ss += v.x*v.x + v.y*v.y + v.z*v.z + v.w*v.w;
    }
    __shared__ float shs[32], shss[32];
    float ws = warpRedSum(s), wss = warpRedSum(ss);
    const int lane = threadIdx.x & 31, wid = threadIdx.x >> 5;
    if (lane == 0) { shs[wid] = ws; shss[wid] = wss; }
    __syncthreads();
    if (wid == 0) {
        float a = (lane < 8) ? shs[lane] : 0.f;
        float b = (lane < 8) ? shss[lane] : 0.f;
        a = warpRedSum(a); b = warpRedSum(b);
        if (lane == 0) {
            float mean = a * (1.f / (float)GELEMS);
            float var  = b * (1.f / (float)GELEMS) - mean * mean;
            g_mu[bg] = mean;
            g_rstd[bg] = rsqrtf(var + EPSV);
        }
    }
}

// ---------------- group-norm apply (elementwise): x[c,n] fp32 -> xnh[c,n] half ----------------
__global__ __launch_bounds__(256) void gn_apply_k(const float* __restrict__ x,
                                                  const float* __restrict__ gamma,
                                                  const float* __restrict__ beta) {
    const size_t i4 = (size_t)blockIdx.x * 256 + threadIdx.x;   // float4 index
    const size_t e  = i4 * 4;
    const int c  = (int)((e >> 12) & (C - 1));                  // NPIX = 4096 = 2^12
    const int bg = (int)(e >> 15);                              // per group: 8ch*4096 = 32768 = 2^15
    const float sc = gamma[c] * g_rstd[bg];
    const float sh = beta[c] - g_mu[bg] * sc;
    float4 v = reinterpret_cast<const float4*>(x)[i4];
    __half* dst = g_xnh + e;
    *reinterpret_cast<__half2*>(dst) =
        __floats2half2_rn(fmaf(v.x, sc, sh), fmaf(v.y, sc, sh));
    *reinterpret_cast<__half2*>(dst + 2) =
        __floats2half2_rn(fmaf(v.z, sc, sh), fmaf(v.w, sc, sh));
}

// ---------------- rowsum reduce: partial[64][B*N] -> rowsum[B*N] ----------------
__global__ __launch_bounds__(256) void reduce_rowsum_k() {
    const int idx = blockIdx.x * 256 + threadIdx.x;           // < BATCH*NPIX
    float s = 0.f;
    #pragma unroll
    for (int i = 0; i < 64; i++)
        s += g_partial[(size_t)i * (BATCH * NPIX) + idx];
    g_rowsum[idx] = s;
}

// ---------------- fp16 tensor GEMM, 4-stage cp.async + ldmatrix(.trans) ----------------
// D[m,n] = sum_k A(m,k) * B(n,k).
//   AT=false: A stored [m][k] k-contig (lda = k-stride). AT=true: A stored [k][m] m-contig (lda = row stride).
//   BT likewise for B with n<->m.
// Epilogue MODE: 0 fp32+bias | 1 half+bias | 2 half exp(D/16-SHIFT)+rowsum partials | 3 half D/rowsum.
// Block tile 128x128, KTILE=32, 8 warps (4m x 2n), warp tile 32x64.
#define HKT    32
#define NSTR   40                            // non-trans row stride (halves)
#define TSTR   136                           // trans row stride (halves)
#define STAGES 4

template<int MODE, bool AT, bool BT>
__global__ __launch_bounds__(256)
void hgemm_k(const __half* __restrict__ A, const __half* __restrict__ B,
             const float* __restrict__ bias, const float* __restrict__ aux,
             float* __restrict__ auxw, void* __restrict__ Cg,
             int lda, int ldb, int ldc, int K,
             long long sA, long long sB, long long sC)
{
    constexpr int A_TH  = AT ? (HKT * TSTR) : (128 * NSTR);   // halves per A tile
    constexpr int B_TH  = BT ? (HKT * TSTR) : (128 * NSTR);
    constexpr int STG_H = A_TH + B_TH;

    extern __shared__ __half sm[];
    const uint32_t smem_b = (uint32_t)__cvta_generic_to_shared(sm);

    const int t = threadIdx.x, wid = t >> 5, lane = t & 31;
    const int g = lane >> 2, tq = lane & 3;
    const int wm = (wid >> 1) * 32;         // 4 warps along m
    const int wn = (wid & 1) * 64;          // 2 warps along n
    const int bm = blockIdx.y * 128;
    const int bn = blockIdx.x * 128;
    A += (long long)blockIdx.z * sA + (AT ? (long long)bm : (long long)bm * lda);
    B += (long long)blockIdx.z * sB + (BT ? (long long)bn : (long long)bn * ldb);

    // per-thread cp.async source/dest geometry
    const int nt_r = t >> 2, nt_c = (t & 3) << 3;   // non-trans: 128 rows x 4 chunks (2 iters of 64 rows... see below)
    const int tr_r = t >> 4, tr_c = (t & 15) << 3;  // trans: 32 rows x 16 chunks (2 iters of 16 rows)

    // ldmatrix per-lane base offsets (halves, within a stage)
    uint32_t a_off[2], b_off[4];
    #pragma unroll
    for (int mf = 0; mf < 2; mf++) {
        if (AT) // rows k: (L&7)+((L&16)?8:0); col m: +((L&8)?8:0)
            a_off[mf] = (uint32_t)(((lane & 7) + ((lane & 16) ? 8 : 0)) * TSTR
                                   + wm + mf * 16 + ((lane & 8) ? 8 : 0));
        else    // rows m: (L&15); k-half: (L>>4)*8
            a_off[mf] = (uint32_t)((wm + mf * 16 + (lane & 15)) * NSTR + ((lane >> 4) * 8));
    }
    #pragma unroll
    for (int p = 0; p < 4; p++) {
        if (BT) // rows k: (L&7)+((L&8)?8:0); col n: +((L&16)?8:0)
            b_off[p] = (uint32_t)(((lane & 7) + ((lane & 8) ? 8 : 0)) * TSTR
                                  + wn + p * 16 + ((lane & 16) ? 8 : 0)) + A_TH;
        else    // rows n: p*16 + ((L&16)?8:0)+(L&7); k-half: (L&8)?8:0
            b_off[p] = (uint32_t)((wn + p * 16 + ((lane & 16) ? 8 : 0) + (lane & 7)) * NSTR
                                  + ((lane & 8) ? 8 : 0)) + A_TH;
    }

    float acc[2][8][4];
    #pragma unroll
    for (int i = 0; i < 2; i++)
        #pragma unroll
        for (int j = 0; j < 8; j++)
            #pragma unroll
            for (int r = 0; r < 4; r++) acc[i][j][r] = 0.f;

    const int T = K / HKT;

    // stage loader
    auto load_stage = [&](int s, int k0) {
        const uint32_t sb = smem_b + (uint32_t)s * (STG_H * 2);
        #pragma unroll
        for (int i = 0; i < 2; i++) {
            if (AT) {
                const int r = tr_r + 16 * i;
                CPA16(sb + (uint32_t)(r * TSTR + tr_c) * 2, &A[(long long)(k0 + r) * lda + tr_c]);
            } else {
                const int r = nt_r + 64 * i;
                CPA16(sb + (uint32_t)(r * NSTR + nt_c) * 2, &A[(long long)r * lda + k0 + nt_c]);
            }
            if (BT) {
                const int r = tr_r + 16 * i;
                CPA16(sb + (uint32_t)(A_TH + r * TSTR + tr_c) * 2, &B[(long long)(k0 + r) * ldb + tr_c]);
            } else {
                const int r = nt_r + 64 * i;
                CPA16(sb + (uint32_t)(A_TH + r * NSTR + nt_c) * 2, &B[(long long)r * ldb + k0 + nt_c]);
            }
        }
        CPA_COMMIT();
    };

    // prologue: stages 0..STAGES-2
    #pragma unroll
    for (int s = 0; s < STAGES - 1; s++) load_stage(s, s * HKT);

    int slot = 0;
    for (int kt = 0; kt < T; kt++) {
        CPA_WAIT(STAGES - 2);
        __syncthreads();

        if (kt + STAGES - 1 < T) {
            const int ws = (slot + STAGES - 1 >= STAGES) ? slot - 1 : slot + STAGES - 1;
            load_stage(ws, (kt + STAGES - 1) * HKT);
        }

        // compute on slot
        {
            const uint32_t sbase = smem_b + (uint32_t)slot * (STG_H * 2);
            #pragma unroll
            for (int ks = 0; ks < HKT; ks += 16) {
                uint32_t af[2][4], bf[8][2];
                #pragma unroll
                for (int mf = 0; mf < 2; mf++) {
                    const uint32_t ad = sbase + (a_off[mf] + (AT ? ks * TSTR : ks)) * 2;
                    if (AT) { LDSM_X4_T(af[mf][0], af[mf][1], af[mf][2], af[mf][3], ad); }
                    else    { LDSM_X4  (af[mf][0], af[mf][1], af[mf][2], af[mf][3], ad); }
                }
                #pragma unroll
                for (int p = 0; p < 4; p++) {
                    const uint32_t bd = sbase + (b_off[p] + (BT ? ks * TSTR : ks)) * 2;
                    if (BT) { LDSM_X4_T(bf[2*p][0], bf[2*p][1], bf[2*p+1][0], bf[2*p+1][1], bd); }
                    else    { LDSM_X4  (bf[2*p][0], bf[2*p][1], bf[2*p+1][0], bf[2*p+1][1], bd); }
                }
                #pragma unroll
                for (int mf = 0; mf < 2; mf++)
                    #pragma unroll
                    for (int nf = 0; nf < 8; nf++)
                        MMA_F16(acc[mf][nf], af[mf], bf[nf]);
            }
        }
        slot = (slot + 1 == STAGES) ? 0 : slot + 1;
    }

    // ---- epilogue ----
    float psum[2][2];
    if (MODE == 2) {
        psum[0][0] = psum[0][1] = psum[1][0] = psum[1][1] = 0.f;
        #pragma unroll
        for (int mf = 0; mf < 2; mf++)
            #pragma unroll
            for (int nf = 0; nf < 8; nf++)
                #pragma unroll
                for (int r = 0; r < 4; r++) {
                    const float e = __expf(fmaf(acc[mf][nf][r], 0.0625f, -EXP_SHIFT));
                    acc[mf][nf][r] = e;
                    psum[mf][r >> 1] += e;
                }
    }

    #pragma unroll
    for (int mf = 0; mf < 2; mf++)
        #pragma unroll
        for (int h = 0; h < 2; h++) {
            const long long row = bm + wm + mf * 16 + g + 8 * h;
            float bv = 0.f, scl = 1.f;
            if (MODE == 0 || MODE == 1) bv = __ldg(&bias[row]);
            if (MODE == 3) scl = 1.f / __ldg(&aux[(size_t)blockIdx.z * NPIX + row]);
            #pragma unroll
            for (int nf = 0; nf < 8; nf++) {
                const long long col = bn + wn + nf * 8 + 2 * tq;
                float vx = acc[mf][nf][2 * h];
                float vy = acc[mf][nf][2 * h + 1];
                if (MODE == 0 || MODE == 1) { vx += bv; vy += bv; }
                if (MODE == 3)              { vx *= scl; vy *= scl; }
                if (MODE == 0) {
                    float* Cf = (float*)Cg + (long long)blockIdx.z * sC;
                    *reinterpret_cast<float2*>(&Cf[row * ldc + col]) = make_float2(vx, vy);
                } else {
                    __half* Ch = (__half*)Cg + (long long)blockIdx.z * sC;
                    *reinterpret_cast<__half2*>(&Ch[row * ldc + col]) = __floats2half2_rn(vx, vy);
                }
            }
        }

    if (MODE == 2) {
        #pragma unroll
        for (int mf = 0; mf < 2; mf++)
            #pragma unroll
            for (int h = 0; h < 2; h++) {
                float s = psum[mf][h];
                s += __shfl_xor_sync(0xffffffffu, s, 1);
                s += __shfl_xor_sync(0xffffffffu, s, 2);
                if (tq == 0) {
                    const int slot2 = blockIdx.x * 2 + (wid & 1);   // 64 slots
                    const long long row = bm + wm + mf * 16 + g + 8 * h;
                    auxw[(size_t)slot2 * (BATCH * NPIX) + (size_t)blockIdx.z * NPIX + row] = s;
                }
            }
    }
}

// smem bytes per instantiation
static constexpr int smem_bytes(bool AT, bool BT) {
    return STAGES * ((AT ? HKT * TSTR : 128 * NSTR) + (BT ? HKT * TSTR : 128 * NSTR)) * 2;
}

// ---------------- launch ----------------
extern "C" void kernel_launch(void* const* d_in, const int* in_sizes, int n_in,
                              void* d_out, int out_size) {
    (void)in_sizes; (void)n_in; (void)out_size;
    const float* x        = (const float*)d_in[0];
    const float* gn_gamma = (const float*)d_in[1];
    const float* gn_beta  = (const float*)d_in[2];
    const float* w_qkv    = (const float*)d_in[3];
    const float* b_qkv    = (const float*)d_in[4];
    const float* w_out    = (const float*)d_in[5];
    const float* b_out    = (const float*)d_in[6];
    float* out = (float*)d_out;

    __half *xnh, *qkvh, *ph, *oth, *wqh, *woh;
    float *partial, *rowsum;
    cudaGetSymbolAddress((void**)&xnh,     g_xnh);
    cudaGetSymbolAddress((void**)&qkvh,    g_qkvh);
    cudaGetSymbolAddress((void**)&ph,      g_ph);
    cudaGetSymbolAddress((void**)&oth,     g_oth);
    cudaGetSymbolAddress((void**)&wqh,     g_wqh);
    cudaGetSymbolAddress((void**)&woh,     g_woh);
    cudaGetSymbolAddress((void**)&partial, g_partial);
    cudaGetSymbolAddress((void**)&rowsum,  g_rowsum);

    constexpr int SM_QKV = smem_bytes(false, true);    // 75776
    constexpr int SM_SC  = smem_bytes(true,  true);    // 69632
    constexpr int SM_NN  = smem_bytes(false, false);   // 81920
    cudaFuncSetAttribute(hgemm_k<1, false, true >, cudaFuncAttributeMaxDynamicSharedMemorySize, SM_QKV);
    cudaFuncSetAttribute(hgemm_k<2, true,  true >, cudaFuncAttributeMaxDynamicSharedMemorySize, SM_SC);
    cudaFuncSetAttribute(hgemm_k<3, false, false>, cudaFuncAttributeMaxDynamicSharedMemorySize, SM_NN);
    cudaFuncSetAttribute(hgemm_k<0, false, false>, cudaFuncAttributeMaxDynamicSharedMemorySize, SM_NN);

    // 1) group-norm stats + weight conversion (fused launch)
    gn_stats_convw_k<<<BATCH * GROUPS + 256, 256>>>(x, w_qkv, w_out);

    // 2) GN apply (elementwise) -> xnh [c, n] half
    gn_apply_k<<<(BATCH * C * NPIX) / (4 * 256), 256>>>(x, gn_gamma, gn_beta);

    // 3) qkv[o,n] half = Wqkv[o,c] . xn[c,n] + b_qkv   (B trans-loaded)
    hgemm_k<1, false, true><<<dim3(NPIX / 128, (3 * C) / 128, BATCH), 256, SM_QKV>>>(
        wqh, xnh, b_qkv, nullptr, nullptr, qkvh, C, NPIX, NPIX, C,
        0LL, (long long)C * NPIX, (long long)3 * C * NPIX);

    // 4) scores+exp: Ph[j,i] = exp(Q[:,j].K[:,i]/16 - SHIFT); partial row sums
    //    (A = Q [c,j] trans, B = K [c,i] trans, straight from qkv)
    hgemm_k<2, true, true><<<dim3(NPIX / 128, NPIX / 128, BATCH), 256, SM_SC>>>(
        qkvh, qkvh + (size_t)C * NPIX, nullptr, nullptr, partial, ph,
        NPIX, NPIX, NPIX, C,
        (long long)3 * C * NPIX, (long long)3 * C * NPIX, (long long)NPIX * NPIX);

    // 5) rowsum[b,j] = sum of 64 partials
    reduce_rowsum_k<<<BATCH * NPIX / 256, 256>>>();

    // 6) O^T[j,c] half = (Ph[j,:] . V[c,:]^T) / rowsum[b,j]   (K = 4096)
    hgemm_k<3, false, false><<<dim3(C / 128, NPIX / 128, BATCH), 256, SM_NN>>>(
        ph, qkvh + (size_t)2 * C * NPIX, nullptr, rowsum, nullptr, oth,
        NPIX, NPIX, C, NPIX,
        (long long)NPIX * NPIX, (long long)3 * C * NPIX, (long long)NPIX * C);

    // 7) out[o,j] fp32 = Wout[o,c] . OT[j,c]^T + b_out
    hgemm_k<0, false, false><<<dim3(NPIX / 128, C / 128, BATCH), 256, SM_NN>>>(
        woh, oth, b_out, nullptr, nullptr, out, C, C, NPIX, C,
        0LL, (long long)NPIX * C, (long long)C * NPIX);
}